// round 12
// baseline (speedup 1.0000x reference)
#include <cuda_runtime.h>
#include <math.h>

#define NB 4
#define NPTS 4096
#define KNN 16
#define DPf 64
#define DMf 128
#define M1 (NB*NPTS)          /* 16384  */
#define M2 (M1*KNN)           /* 262144 */
#define EPSV 1e-8f
#define PITCH 132             /* smem tile pitch; 4*132=528 words, %32=16 -> conflict-free */
#define BROWS 64

// ---------------- scratch ----------------
__device__ float g_q [(size_t)M1*DMf];
__device__ float g_kf[(size_t)M1*DMf];
__device__ float g_vf[(size_t)M1*DMf];
__device__ float g_qs[(size_t)M1*DMf];
__device__ float g_ks[(size_t)M1*DMf];
__device__ float g_cw[5*65*DMf];         // combined weights: [fc1;fc1_b]@{wq,wk,wv,wq@simw',wk@simw'}
__device__ int   g_idx[M1*KNN];

// ---------------- packed f32x2 helpers ----------------
__device__ __forceinline__ unsigned long long pack2(float x, float y) {
    unsigned long long r;
    asm("mov.b64 %0, {%1, %2};" : "=l"(r) : "f"(x), "f"(y));
    return r;
}
__device__ __forceinline__ float2 unpack2(unsigned long long v) {
    float2 f;
    asm("mov.b64 {%0, %1}, %2;" : "=f"(f.x), "=f"(f.y) : "l"(v));
    return f;
}
__device__ __forceinline__ void ffma2(unsigned long long& d,
                                      unsigned long long a,
                                      unsigned long long b) {
    asm("fma.rn.f32x2 %0, %1, %2, %0;" : "+l"(d) : "l"(a), "l"(b));
}

// ---------------- cp.async helpers ----------------
__device__ __forceinline__ unsigned smem_u32(const void* p) {
    unsigned a;
    asm("{ .reg .u64 t; cvta.to.shared.u64 t, %1; cvt.u32.u64 %0, t; }" : "=r"(a) : "l"(p));
    return a;
}
__device__ __forceinline__ void cpa16(unsigned dst, const void* src) {
    asm volatile("cp.async.ca.shared.global [%0], [%1], 16;" :: "r"(dst), "l"(src));
}
__device__ __forceinline__ void cpa_commit() { asm volatile("cp.async.commit_group;"); }
template<int N> __device__ __forceinline__ void cpa_wait() {
    asm volatile("cp.async.wait_group %0;" :: "n"(N));
}

// ---------------- KNN: warp per query, branchless register top-16 ----------------
__global__ void knn_kernel(const float* __restrict__ xyz) {
    int warp = threadIdx.x >> 5;
    int lane = threadIdx.x & 31;
    int row  = blockIdx.x * 4 + warp;
    int b = row >> 12;
    int n = row & (NPTS - 1);
    const float* xb = xyz + (size_t)b * NPTS * 3;
    float qx = xb[n*3+0], qy = xb[n*3+1], qz = xb[n*3+2];
    float sq = qx*qx + qy*qy + qz*qz;

    unsigned long long best[16];
#pragma unroll
    for (int i = 0; i < 16; i++) best[i] = ~0ULL;

    for (int t = 0; t < NPTS/32; t++) {
        int j = t*32 + lane;
        float x = xb[j*3+0], y = xb[j*3+1], z = xb[j*3+2];
        float sj = x*x + y*y + z*z;
        float d = sq + sj - 2.0f*(qx*x + qy*y + qz*z);
        unsigned u = __float_as_uint(d);
        u = (u & 0x80000000u) ? ~u : (u | 0x80000000u);
        unsigned long long key = ((unsigned long long)u << 32) | (unsigned)j;

        bool pi = key < best[15];
#pragma unroll
        for (int i = 15; i >= 1; i--) {
            bool pim = key < best[i-1];
            best[i] = pi ? (pim ? best[i-1] : key) : best[i];
            pi = pim;
        }
        best[0] = pi ? key : best[0];
    }

    __shared__ unsigned long long sh[4][512];
#pragma unroll
    for (int i = 0; i < 16; i++) sh[warp][lane*16 + i] = best[i];
    __syncwarp();

    int p = 0;
    for (int r = 0; r < 16; r++) {
        unsigned long long v = (p < 16) ? sh[warp][lane*16 + p] : ~0ULL;
        unsigned long long m = v;
#pragma unroll
        for (int off = 16; off; off >>= 1) {
            unsigned long long o = __shfl_xor_sync(0xffffffffu, m, off);
            m = (o < m) ? o : m;
        }
        if (v == m) { g_idx[row*KNN + r] = (int)(m & 0xffffffffu); p++; }
        __syncwarp();
    }
}

// ---------------- prep A: cw_w = [fc1_w ; fc1_b] @ W   (65x128, w = 0..2) ----------------
__global__ void __launch_bounds__(256)
prep_cw(const float* __restrict__ fc1_w, const float* __restrict__ fc1_b,
        const float* __restrict__ wq, const float* __restrict__ wk,
        const float* __restrict__ wv) {
    const float* W = (blockIdx.x == 0) ? wq : (blockIdx.x == 1) ? wk : wv;
    float* C = g_cw + (size_t)blockIdx.x * 65 * DMf;

    __shared__ float sA[64*128];
    __shared__ float sb[128];
    for (int i = threadIdx.x; i < 64*128/4; i += 256)
        ((float4*)sA)[i] = ((const float4*)fc1_w)[i];
    if (threadIdx.x < 32)
        ((float4*)sb)[threadIdx.x] = ((const float4*)fc1_b)[threadIdx.x];
    __syncthreads();

    int c    = threadIdx.x & 127;
    int half = threadIdx.x >> 7;         // rows half, half+2, ...
    float acc[33];
#pragma unroll
    for (int i = 0; i < 33; i++) acc[i] = 0.0f;

    for (int k = 0; k < 128; k++) {
        float wkc = W[k*128 + c];
#pragma unroll
        for (int i = 0; i < 32; i++)
            acc[i] += sA[(half + 2*i)*128 + k] * wkc;   // rows 0..63
        acc[32] += sb[k] * wkc;                          // bias row (only half==0 stores)
    }
#pragma unroll
    for (int i = 0; i < 32; i++)
        C[(half + 2*i)*128 + c] = acc[i];
    if (half == 0) C[64*128 + c] = acc[32];
}

// ---------------- prep B: cw_{qs,ks} = cw_{q,k} @ simw'  (65x128, full-row transform) ----
__global__ void __launch_bounds__(256)
prep_cw2(const float* __restrict__ simw1) {   // sim_w + 128
    const float* A = g_cw + (size_t)blockIdx.x * 65 * DMf;      // cw_q or cw_k
    float* C = g_cw + (size_t)(3 + blockIdx.x) * 65 * DMf;

    __shared__ float sA[65*128];
    for (int i = threadIdx.x; i < 65*128/4; i += 256)
        ((float4*)sA)[i] = ((const float4*)A)[i];
    __syncthreads();

    int c    = threadIdx.x & 127;
    int half = threadIdx.x >> 7;
    float acc[33];
#pragma unroll
    for (int i = 0; i < 33; i++) acc[i] = 0.0f;

    for (int k = 0; k < 128; k++) {
        float wkc = simw1[k*128 + c];
#pragma unroll
        for (int i = 0; i < 32; i++)
            acc[i] += sA[(half + 2*i)*128 + k] * wkc;
        acc[32] += sA[64*128 + k] * wkc;                 // bias row through simw'
    }
#pragma unroll
    for (int i = 0; i < 32; i++)
        C[(half + 2*i)*128 + c] = acc[i];
    if (half == 0) C[64*128 + c] = acc[32];
}

// ---------------- GEMM core ----------------
__device__ __forceinline__ void gemm128_body(const float* __restrict__ A, int lda, int Ka,
                                             const float* __restrict__ W,
                                             const float* __restrict__ bias,
                                             float* __restrict__ C, int bm, int tid) {
    __shared__ float As[32][132];
    __shared__ float Ws[32][128];
    int tm = tid >> 4, tn = tid & 15;

    unsigned long long acc[8][4];
#pragma unroll
    for (int i = 0; i < 8; i++)
#pragma unroll
        for (int j = 0; j < 4; j++) acc[i][j] = 0ULL;

    for (int k0 = 0; k0 < Ka; k0 += 32) {
#pragma unroll
        for (int pss = 0; pss < 4; pss++) {
            int idx4 = pss*256 + tid;
            int r  = idx4 >> 3;
            int c4 = idx4 & 7;
            float4 v = *(const float4*)(A + (size_t)(bm + r)*lda + k0 + c4*4);
            As[c4*4+0][r] = v.x; As[c4*4+1][r] = v.y;
            As[c4*4+2][r] = v.z; As[c4*4+3][r] = v.w;
        }
#pragma unroll
        for (int pss = 0; pss < 4; pss++) {
            int idx4 = pss*256 + tid;
            int r  = idx4 >> 5;
            int c4 = idx4 & 31;
            *(float4*)&Ws[r][c4*4] = *(const float4*)(W + (size_t)(k0 + r)*128 + c4*4);
        }
        __syncthreads();
#pragma unroll
        for (int kk = 0; kk < 32; kk++) {
            float4 a0 = *(const float4*)&As[kk][tm*8];
            float4 a1 = *(const float4*)&As[kk][tm*8 + 4];
            ulonglong2 b01 = *(const ulonglong2*)&Ws[kk][tn*8];
            ulonglong2 b23 = *(const ulonglong2*)&Ws[kk][tn*8+4];
            unsigned long long av[8] = { pack2(a0.x, a0.x), pack2(a0.y, a0.y),
                                         pack2(a0.z, a0.z), pack2(a0.w, a0.w),
                                         pack2(a1.x, a1.x), pack2(a1.y, a1.y),
                                         pack2(a1.z, a1.z), pack2(a1.w, a1.w) };
#pragma unroll
            for (int i = 0; i < 8; i++) {
                ffma2(acc[i][0], av[i], b01.x);
                ffma2(acc[i][1], av[i], b01.y);
                ffma2(acc[i][2], av[i], b23.x);
                ffma2(acc[i][3], av[i], b23.y);
            }
        }
        __syncthreads();
    }

    float bia[8];
#pragma unroll
    for (int j = 0; j < 8; j++) bia[j] = bias ? bias[tn*8 + j] : 0.0f;

#pragma unroll
    for (int i = 0; i < 8; i++) {
        size_t row = (size_t)bm + tm*8 + i;
        float v[8];
#pragma unroll
        for (int j = 0; j < 4; j++) {
            float2 f = unpack2(acc[i][j]);
            v[2*j]   = f.x + bia[2*j];
            v[2*j+1] = f.y + bia[2*j+1];
        }
        float4* cp = (float4*)(C + row*128 + tn*8);
        cp[0] = make_float4(v[0], v[1], v[2], v[3]);
        cp[1] = make_float4(v[4], v[5], v[6], v[7]);
    }
}

// batched 5-way from features with combined weights (Ka = 64, bias = row 64 of cw)
__global__ void __launch_bounds__(256, 2)
gemm_batch5(const float* __restrict__ A) {
    const float* cw = g_cw + (size_t)blockIdx.y * 65 * DMf;
    float* Cs[5] = { g_q, g_kf, g_vf, g_qs, g_ks };
    gemm128_body(A, DPf, DPf, cw, cw + 64*128, Cs[blockIdx.y],
                 blockIdx.x * 128, threadIdx.x);
}

// ---------------- mega kernel ----------------
#define OFF_AS  0
#define OFF_BS  (BROWS*PITCH)
#define OFF_W   (2*BROWS*PITCH)
#define OFF_QS  (OFF_W + 2*32*128)
#define OFF_SIM (OFF_QS + 512)
#define OFF_QN  (OFF_SIM + 64)
#define OFF_IDX (OFF_QN + 4)
#define MEGA_FLOATS (OFF_IDX + 64)

__device__ __forceinline__ void load_quarter(unsigned sW, const float* __restrict__ W,
                                             int quarter, int tid) {
    const float* src = W + (size_t)quarter*32*128;
#pragma unroll
    for (int it = 0; it < 4; it++) {
        int c = it*256 + tid;
        cpa16(sW + (unsigned)c*16u, src + c*4);
    }
}

__device__ __forceinline__ void mm32(const float* __restrict__ T, int kbase,
                                     const float* __restrict__ W,
                                     int tm, int tn,
                                     unsigned long long acc[4][4]) {
    const float* ap = T + tm*4*PITCH + kbase;
    const float* wp = W + tn*4;
#pragma unroll 4
    for (int kk = 0; kk < 32; kk += 2) {
        ulonglong2 B00 = *(const ulonglong2*)(wp + kk*128);
        ulonglong2 B01 = *(const ulonglong2*)(wp + kk*128 + 64);
        ulonglong2 B10 = *(const ulonglong2*)(wp + (kk+1)*128);
        ulonglong2 B11 = *(const ulonglong2*)(wp + (kk+1)*128 + 64);
#pragma unroll
        for (int i = 0; i < 4; i++) {
            float2 a = *(const float2*)(ap + i*PITCH + kk);
            unsigned long long av0 = pack2(a.x, a.x);
            unsigned long long av1 = pack2(a.y, a.y);
            ffma2(acc[i][0], av0, B00.x);
            ffma2(acc[i][1], av0, B00.y);
            ffma2(acc[i][2], av0, B01.x);
            ffma2(acc[i][3], av0, B01.y);
            ffma2(acc[i][0], av1, B10.x);
            ffma2(acc[i][1], av1, B10.y);
            ffma2(acc[i][2], av1, B11.x);
            ffma2(acc[i][3], av1, B11.y);
        }
    }
}

__global__ void __launch_bounds__(256, 2)
mega_kernel(const float* __restrict__ xyz,
            const float* __restrict__ d1_w, const float* __restrict__ d1_b,
            const float* __restrict__ d2_w, const float* __restrict__ d2_b,
            const float* __restrict__ sim_w, const float* __restrict__ sim_b,
            const float* __restrict__ g1_w, const float* __restrict__ g1_b,
            const float* __restrict__ g2_w, const float* __restrict__ g2_b,
            const float* __restrict__ fc2_w, const float* __restrict__ fc2_b,
            const float* __restrict__ features,
            float* __restrict__ out) {
    extern __shared__ float sm[];
    float* As   = sm + OFF_AS;
    float* Bs   = sm + OFF_BS;
    float* Wb   = sm + OFF_W;
    float* Qs   = sm + OFF_QS;
    float* ssim = sm + OFF_SIM;
    float* sqn  = sm + OFF_QN;
    int*   sidx = (int*)(sm + OFF_IDX);
    unsigned sW = smem_u32(Wb);

    int tid  = threadIdx.x;
    int wid  = tid >> 5, lane = tid & 31;
    int tm   = tid >> 4, tn = tid & 15;
    int m0   = blockIdx.x * 4;
    size_t bm = (size_t)blockIdx.x * BROWS;
    int b    = m0 >> 12;

    const float* Wseq[3] = { d2_w, g1_w, g2_w };

    load_quarter(sW, Wseq[0], 0, tid);
    cpa_commit();

    // ---- gather prologue ----
    if (tid < 64) sidx[tid] = g_idx[m0*KNN + tid];
    {
        float2 v = *(const float2*)(g_q + (size_t)m0*DMf + tid*2);
        *(float2*)(Qs + tid*2) = v;
    }
    __syncthreads();

    if (wid < 4) {
        float4 qf = *(const float4*)(Qs + wid*128 + lane*4);
        float s = qf.x*qf.x + qf.y*qf.y + qf.z*qf.z + qf.w*qf.w;
#pragma unroll
        for (int off = 16; off; off >>= 1) s += __shfl_xor_sync(0xffffffffu, s, off);
        if (lane == 0) sqn[wid] = fmaxf(sqrtf(s), EPSV);
    }
    __syncthreads();

    float4 w0 = *(const float4*)(d1_w + lane*4);
    float4 w1 = *(const float4*)(d1_w + 128 + lane*4);
    float4 w2 = *(const float4*)(d1_w + 256 + lane*4);
    float4 db = *(const float4*)(d1_b + lane*4);
    const float* xb = xyz + (size_t)b*NPTS*3;

#pragma unroll 1
    for (int it = 0; it < 8; it++) {
        int j   = it*8 + wid;
        int row = j >> 4;
        int n   = (m0 + row) & (NPTS - 1);
        int idx = sidx[j];

        float4 kf = *(const float4*)(g_kf + ((size_t)(b*NPTS + idx))*DMf + lane*4);
        float4 qf = *(const float4*)(Qs + row*128 + lane*4);
        float dq = qf.x*kf.x + qf.y*kf.y + qf.z*kf.z + qf.w*kf.w;
        float dk = kf.x*kf.x + kf.y*kf.y + kf.z*kf.z + kf.w*kf.w;
#pragma unroll
        for (int off = 16; off; off >>= 1) {
            dq += __shfl_xor_sync(0xffffffffu, dq, off);
            dk += __shfl_xor_sync(0xffffffffu, dk, off);
        }
        float kn = fmaxf(sqrtf(dk), EPSV);
        if (lane == 0) ssim[j] = dq / (sqn[row] * kn);

        float cx = xb[n*3+0] - xb[idx*3+0];
        float cy = xb[n*3+1] - xb[idx*3+1];
        float cz = xb[n*3+2] - xb[idx*3+2];
        float4 h;
        h.x = fmaxf(cx*w0.x + cy*w1.x + cz*w2.x + db.x, 0.0f);
        h.y = fmaxf(cx*w0.y + cy*w1.y + cz*w2.y + db.y, 0.0f);
        h.z = fmaxf(cx*w0.z + cy*w1.z + cz*w2.z + db.z, 0.0f);
        h.w = fmaxf(cx*w0.w + cy*w1.w + cz*w2.w + db.w, 0.0f);
        *(float4*)(As + j*PITCH + lane*4) = h;
    }

    // ---- 3-GEMM chain, one sync per quarter ----
    unsigned long long acc[4][4];
#pragma unroll
    for (int i = 0; i < 4; i++)
#pragma unroll
        for (int j = 0; j < 4; j++) acc[i][j] = 0ULL;

    int ch = 0;
    for (int g = 0; g < 3; g++) {
        if (g >= 1) {
#pragma unroll
            for (int i = 0; i < 4; i++)
#pragma unroll
                for (int j = 0; j < 4; j++) acc[i][j] = 0ULL;
        }
        const float* tile = (g == 0) ? As : Bs;
        for (int q = 0; q < 4; q++) {
            cpa_wait<0>();
            __syncthreads();
            int nxt = ch + 1;
            if (nxt < 12) {
                load_quarter(sW + (unsigned)((nxt & 1)*4096)*4u, Wseq[nxt >> 2], nxt & 3, tid);
                cpa_commit();
            }
            mm32(tile, q*32, Wb + (ch & 1)*4096, tm, tn, acc);
            ch++;
        }

        if (g == 0) {
            float4 b0 = *(const float4*)(d2_b + tn*4);
            float4 b1 = *(const float4*)(d2_b + 64 + tn*4);
            float4 sb0 = *(const float4*)(sim_b + tn*4);
            float4 sb1 = *(const float4*)(sim_b + 64 + tn*4);
            float4 s0 = *(const float4*)(sim_w + tn*4);
            float4 s1 = *(const float4*)(sim_w + 64 + tn*4);
            float bb[8]  = {b0.x,b0.y,b0.z,b0.w,b1.x,b1.y,b1.z,b1.w};
            float sbb[8] = {sb0.x,sb0.y,sb0.z,sb0.w,sb1.x,sb1.y,sb1.z,sb1.w};
            float sw[8]  = {s0.x,s0.y,s0.z,s0.w,s1.x,s1.y,s1.z,s1.w};
#pragma unroll
            for (int i = 0; i < 4; i++) {
                int r = tm*4 + i;
                float sv = ssim[r];
                const float* qsp = g_qs + (size_t)(m0 + (r >> 4))*DMf;
                const float* ksp = g_ks + ((size_t)(b*NPTS + sidx[r]))*DMf;
                float4 q0 = *(const float4*)(qsp + tn*4);
                float4 q1 = *(const float4*)(qsp + 64 + tn*4);
                float4 k0 = *(const float4*)(ksp + tn*4);
                float4 k1 = *(const float4*)(ksp + 64 + tn*4);
                float qs8[8] = {q0.x,q0.y,q0.z,q0.w,q1.x,q1.y,q1.z,q1.w};
                float ks8[8] = {k0.x,k0.y,k0.z,k0.w,k1.x,k1.y,k1.z,k1.w};
                float pe[8], t[8];
#pragma unroll
                for (int j = 0; j < 4; j++) {
                    float2 f = unpack2(acc[i][j]);
                    pe[2*j]   = f.x + bb[2*j];
                    pe[2*j+1] = f.y + bb[2*j+1];
                }
#pragma unroll
                for (int s = 0; s < 8; s++)
                    t[s] = pe[s] + qs8[s] - ks8[s] + sv*sw[s] + sbb[s];
                *(float4*)&As[r*PITCH + tn*4]      = make_float4(pe[0],pe[1],pe[2],pe[3]);
                *(float4*)&As[r*PITCH + 64 + tn*4] = make_float4(pe[4],pe[5],pe[6],pe[7]);
                *(float4*)&Bs[r*PITCH + tn*4]      = make_float4(t[0],t[1],t[2],t[3]);
                *(float4*)&Bs[r*PITCH + 64 + tn*4] = make_float4(t[4],t[5],t[6],t[7]);
            }
        } else if (g == 1) {
            float4 b0 = *(const float4*)(g1_b + tn*4);
            float4 b1 = *(const float4*)(g1_b + 64 + tn*4);
            float bb[8] = {b0.x,b0.y,b0.z,b0.w,b1.x,b1.y,b1.z,b1.w};
#pragma unroll
            for (int i = 0; i < 4; i++) {
                int r = tm*4 + i;
                float v[8];
#pragma unroll
                for (int j = 0; j < 4; j++) {
                    float2 f = unpack2(acc[i][j]);
                    v[2*j]   = fmaxf(f.x + bb[2*j],   0.0f);
                    v[2*j+1] = fmaxf(f.y + bb[2*j+1], 0.0f);
                }
                *(float4*)&Bs[r*PITCH + tn*4]      = make_float4(v[0],v[1],v[2],v[3]);
                *(float4*)&Bs[r*PITCH + 64 + tn*4] = make_float4(v[4],v[5],v[6],v[7]);
            }
        }
    }
    __syncthreads();

    // ---- epilogue: softmax(k) + attn out + weighted sum + fc2 + residual ----
    {
        const float scale = 0.08838834764831845f;
        int q = tm >> 2;
        int mb = q*4;

        float sc[4][8];
        {
            float4 b0 = *(const float4*)(g2_b + tn*4);
            float4 b1 = *(const float4*)(g2_b + 64 + tn*4);
            float bb[8] = {b0.x,b0.y,b0.z,b0.w,b1.x,b1.y,b1.z,b1.w};
#pragma unroll
            for (int i = 0; i < 4; i++)
#pragma unroll
                for (int j = 0; j < 4; j++) {
                    float2 f = unpack2(acc[i][j]);
                    sc[i][2*j]   = (f.x + bb[2*j])   * scale;
                    sc[i][2*j+1] = (f.y + bb[2*j+1]) * scale;
                }
        }
        {
            float m4[8];
#pragma unroll
            for (int s = 0; s < 8; s++)
                m4[s] = fmaxf(fmaxf(sc[0][s], sc[1][s]), fmaxf(sc[2][s], sc[3][s]));
            *(float4*)&Bs[tm*128 + tn*4]      = make_float4(m4[0],m4[1],m4[2],m4[3]);
            *(float4*)&Bs[tm*128 + 64 + tn*4] = make_float4(m4[4],m4[5],m4[6],m4[7]);
        }
        __syncthreads();
        float mx[8];
#pragma unroll
        for (int s = 0; s < 8; s++) {
            int col = (s < 4) ? tn*4 + s : 64 + tn*4 + (s-4);
            float a0 = Bs[(mb+0)*128 + col];
            float a1 = Bs[(mb+1)*128 + col];
            float a2 = Bs[(mb+2)*128 + col];
            float a3 = Bs[(mb+3)*128 + col];
            mx[s] = fmaxf(fmaxf(a0,a1), fmaxf(a2,a3));
        }
        float e[4][8], ps[8];
#pragma unroll
        for (int s = 0; s < 8; s++) {
            float p = 0.0f;
#pragma unroll
            for (int i = 0; i < 4; i++) { e[i][s] = expf(sc[i][s] - mx[s]); p += e[i][s]; }
            ps[s] = p;
        }
        *(float4*)&Bs[2048 + tm*128 + tn*4]      = make_float4(ps[0],ps[1],ps[2],ps[3]);
        *(float4*)&Bs[2048 + tm*128 + 64 + tn*4] = make_float4(ps[4],ps[5],ps[6],ps[7]);
        __syncthreads();
        float inv[8];
#pragma unroll
        for (int s = 0; s < 8; s++) {
            int col = (s < 4) ? tn*4 + s : 64 + tn*4 + (s-4);
            float su = Bs[2048 + (mb+0)*128 + col] + Bs[2048 + (mb+1)*128 + col]
                     + Bs[2048 + (mb+2)*128 + col] + Bs[2048 + (mb+3)*128 + col];
            inv[s] = 1.0f / su;
        }

        float pr[8];
#pragma unroll
        for (int s = 0; s < 8; s++) pr[s] = 0.0f;
        float* outA = out + (size_t)M1*DPf;
#pragma unroll
        for (int i = 0; i < 4; i++) {
            int r = tm*4 + i;
            const float* vp = g_vf + ((size_t)(b*NPTS + sidx[r]))*DMf;
            float a0 = e[i][0]*inv[0], a1 = e[i][1]*inv[1],
                  a2 = e[i][2]*inv[2], a3 = e[i][3]*inv[3];
            float a4 = e[i][4]*inv[4], a5 = e[i][5]*inv[5],
                  a6 = e[i][6]*inv[6], a7 = e[i][7]*inv[7];
            float4 v0 = *(const float4*)(vp + tn*4);
            float4 v1 = *(const float4*)(vp + 64 + tn*4);
            float4 p0 = *(const float4*)&As[r*PITCH + tn*4];
            float4 p1 = *(const float4*)&As[r*PITCH + 64 + tn*4];
            *(float4*)(outA + (bm + r)*128 + tn*4)      = make_float4(a0,a1,a2,a3);
            *(float4*)(outA + (bm + r)*128 + 64 + tn*4) = make_float4(a4,a5,a6,a7);
            pr[0] += a0*(v0.x+p0.x); pr[1] += a1*(v0.y+p0.y);
            pr[2] += a2*(v0.z+p0.z); pr[3] += a3*(v0.w+p0.w);
            pr[4] += a4*(v1.x+p1.x); pr[5] += a5*(v1.y+p1.y);
            pr[6] += a6*(v1.z+p1.z); pr[7] += a7*(v1.w+p1.w);
        }
        __syncthreads();
        *(float4*)&Bs[tm*128 + tn*4]      = make_float4(pr[0],pr[1],pr[2],pr[3]);
        *(float4*)&Bs[tm*128 + 64 + tn*4] = make_float4(pr[4],pr[5],pr[6],pr[7]);
        __syncthreads();

#pragma unroll
        for (int rep = 0; rep < 2; rep++) {
            int ii  = rep*256 + tid;
            int qq  = ii >> 7;
            int col = ii & 127;
            As[qq*128 + col] = Bs[(qq*4+0)*128 + col] + Bs[(qq*4+1)*128 + col]
                             + Bs[(qq*4+2)*128 + col] + Bs[(qq*4+3)*128 + col];
        }
        __syncthreads();

        {
            int qf = tid >> 6, f = tid & 63;
            const float* rp = As + qf*128;
            float o0 = 0.f, o1 = 0.f, o2 = 0.f, o3 = 0.f;
#pragma unroll 8
            for (int j = 0; j < 128; j += 4) {
                o0 += rp[j]   * fc2_w[ j   *DPf + f];
                o1 += rp[j+1] * fc2_w[(j+1)*DPf + f];
                o2 += rp[j+2] * fc2_w[(j+2)*DPf + f];
                o3 += rp[j+3] * fc2_w[(j+3)*DPf + f];
            }
            float o = fc2_b[f] + ((o0 + o1) + (o2 + o3))
                    + features[(size_t)(m0 + qf)*DPf + f];
            out[(size_t)(m0 + qf)*DPf + f] = o;
        }
    }
}

// ---------------- launch ----------------
extern "C" void kernel_launch(void* const* d_in, const int* in_sizes, int n_in,
                              void* d_out, int out_size) {
    const float* xyz   = (const float*)d_in[0];
    const float* feat  = (const float*)d_in[1];
    const float* fc1_w = (const float*)d_in[2];
    const float* fc1_b = (const float*)d_in[3];
    const float* fc2_w = (const float*)d_in[4];
    const float* fc2_b = (const float*)d_in[5];
    const float* d1_w  = (const float*)d_in[6];
    const float* d1_b  = (const float*)d_in[7];
    const float* d2_w  = (const float*)d_in[8];
    const float* d2_b  = (const float*)d_in[9];
    const float* g1_w  = (const float*)d_in[10];
    const float* g1_b  = (const float*)d_in[11];
    const float* g2_w  = (const float*)d_in[12];
    const float* g2_b  = (const float*)d_in[13];
    const float* wq_w  = (const float*)d_in[14];
    const float* wk_w  = (const float*)d_in[15];
    const float* wv_w  = (const float*)d_in[16];
    const float* sim_w = (const float*)d_in[17];
    const float* sim_b = (const float*)d_in[18];
    float* out = (float*)d_out;

    static bool attr_done = false;
    const int MEGA_SMEM = MEGA_FLOATS * 4;
    if (!attr_done) {
        cudaFuncSetAttribute(mega_kernel,
                             cudaFuncAttributeMaxDynamicSharedMemorySize, MEGA_SMEM);
        attr_done = true;
    }

    // 0) KNN
    knn_kernel<<<M1/4, 128>>>(xyz);

    // 1) combined weights cw_q, cw_k, cw_v = [fc1;fc1_b] @ {wq,wk,wv}
    prep_cw<<<3, 256>>>(fc1_w, fc1_b, wq_w, wk_w, wv_w);

    // 2) cw_qs, cw_ks = cw_{q,k} @ simw'
    prep_cw2<<<2, 256>>>(sim_w + 128);

    // 3) q, k, v, qs, ks directly from features (Ka = 64)
    gemm_batch5<<<dim3(M1/128, 5), 256>>>(feat);

    // 4) mega
    mega_kernel<<<M1/4, 256, MEGA_SMEM>>>(xyz, d1_w, d1_b, d2_w, d2_b,
                                          sim_w, sim_b, g1_w, g1_b, g2_w, g2_b,
                                          fc2_w, fc2_b, feat, out);
}

// round 13
// speedup vs baseline: 1.0468x; 1.0468x over previous
#include <cuda_runtime.h>
#include <math.h>

#define NB 4
#define NPTS 4096
#define KNN 16
#define DPf 64
#define DMf 128
#define M1 (NB*NPTS)          /* 16384  */
#define M2 (M1*KNN)           /* 262144 */
#define EPSV 1e-8f
#define PITCH 132             /* smem tile pitch; 4*132=528 words, %32=16 -> conflict-free */
#define BROWS 64

// ---------------- scratch ----------------
__device__ float g_x [(size_t)M1*DMf];
__device__ float g_q [(size_t)M1*DMf];
__device__ float g_kf[(size_t)M1*DMf];
__device__ float g_vf[(size_t)M1*DMf];
__device__ float g_qs[(size_t)M1*DMf];   // x @ (wq@simw')
__device__ float g_ks[(size_t)M1*DMf];   // x @ (wk@simw')
__device__ float g_wqs[DMf*DMf];         // wq @ simw'
__device__ float g_wks[DMf*DMf];         // wk @ simw'
__device__ int   g_idx[M1*KNN];

// ---------------- packed f32x2 helpers ----------------
__device__ __forceinline__ unsigned long long pack2(float x, float y) {
    unsigned long long r;
    asm("mov.b64 %0, {%1, %2};" : "=l"(r) : "f"(x), "f"(y));
    return r;
}
__device__ __forceinline__ float2 unpack2(unsigned long long v) {
    float2 f;
    asm("mov.b64 {%0, %1}, %2;" : "=f"(f.x), "=f"(f.y) : "l"(v));
    return f;
}
__device__ __forceinline__ void ffma2(unsigned long long& d,
                                      unsigned long long a,
                                      unsigned long long b) {
    asm("fma.rn.f32x2 %0, %1, %2, %0;" : "+l"(d) : "l"(a), "l"(b));
}

// ---------------- cp.async helpers ----------------
__device__ __forceinline__ unsigned smem_u32(const void* p) {
    unsigned a;
    asm("{ .reg .u64 t; cvta.to.shared.u64 t, %1; cvt.u32.u64 %0, t; }" : "=r"(a) : "l"(p));
    return a;
}
__device__ __forceinline__ void cpa16(unsigned dst, const void* src) {
    asm volatile("cp.async.ca.shared.global [%0], [%1], 16;" :: "r"(dst), "l"(src));
}
__device__ __forceinline__ void cpa_commit() { asm volatile("cp.async.commit_group;"); }
template<int N> __device__ __forceinline__ void cpa_wait() {
    asm volatile("cp.async.wait_group %0;" :: "n"(N));
}

// ---------------- KNN: warp/query, register top-16 with early-exit ladder ----------------
__global__ void knn_kernel(const float* __restrict__ xyz) {
    int warp = threadIdx.x >> 5;
    int lane = threadIdx.x & 31;
    int row  = blockIdx.x * 4 + warp;
    int b = row >> 12;
    int n = row & (NPTS - 1);
    const float* xb = xyz + (size_t)b * NPTS * 3;
    float qx = xb[n*3+0], qy = xb[n*3+1], qz = xb[n*3+2];
    float sq = qx*qx + qy*qy + qz*qz;

    unsigned long long best[16];
#pragma unroll
    for (int i = 0; i < 16; i++) best[i] = ~0ULL;

    for (int t = 0; t < NPTS/32; t++) {
        int j = t*32 + lane;
        float x = xb[j*3+0], y = xb[j*3+1], z = xb[j*3+2];
        float sj = x*x + y*y + z*z;
        float d = sq + sj - 2.0f*(qx*x + qy*y + qz*z);
        unsigned u = __float_as_uint(d);
        u = (u & 0x80000000u) ? ~u : (u | 0x80000000u);
        unsigned long long key = ((unsigned long long)u << 32) | (unsigned)j;

        if (key < best[15]) {          // divergent but rare after warmup; regs stay static-indexed
            bool pi = true;
#pragma unroll
            for (int i = 15; i >= 1; i--) {
                bool pim = key < best[i-1];
                best[i] = pi ? (pim ? best[i-1] : key) : best[i];
                pi = pim;
            }
            best[0] = pi ? key : best[0];
        }
    }

    __shared__ unsigned long long sh[4][512];
#pragma unroll
    for (int i = 0; i < 16; i++) sh[warp][lane*16 + i] = best[i];
    __syncwarp();

    int p = 0;
    for (int r = 0; r < 16; r++) {
        unsigned long long v = (p < 16) ? sh[warp][lane*16 + p] : ~0ULL;
        unsigned long long m = v;
#pragma unroll
        for (int off = 16; off; off >>= 1) {
            unsigned long long o = __shfl_xor_sync(0xffffffffu, m, off);
            m = (o < m) ? o : m;
        }
        if (v == m) { g_idx[row*KNN + r] = (int)(m & 0xffffffffu); p++; }
        __syncwarp();
    }
}

// ---------------- GEMM core (shared by variants) ----------------
__device__ __forceinline__ void gemm128_body(const float* __restrict__ A, int lda, int Ka,
                                             const float* __restrict__ W,
                                             const float* __restrict__ bias,
                                             float* __restrict__ C, int bm, int tid) {
    __shared__ float As[32][132];
    __shared__ float Ws[32][128];
    int tm = tid >> 4, tn = tid & 15;

    unsigned long long acc[8][4];
#pragma unroll
    for (int i = 0; i < 8; i++)
#pragma unroll
        for (int j = 0; j < 4; j++) acc[i][j] = 0ULL;

    for (int k0 = 0; k0 < Ka; k0 += 32) {
#pragma unroll
        for (int pss = 0; pss < 4; pss++) {
            int idx4 = pss*256 + tid;
            int r  = idx4 >> 3;
            int c4 = idx4 & 7;
            float4 v = *(const float4*)(A + (size_t)(bm + r)*lda + k0 + c4*4);
            As[c4*4+0][r] = v.x; As[c4*4+1][r] = v.y;
            As[c4*4+2][r] = v.z; As[c4*4+3][r] = v.w;
        }
#pragma unroll
        for (int pss = 0; pss < 4; pss++) {
            int idx4 = pss*256 + tid;
            int r  = idx4 >> 5;
            int c4 = idx4 & 31;
            *(float4*)&Ws[r][c4*4] = *(const float4*)(W + (size_t)(k0 + r)*128 + c4*4);
        }
        __syncthreads();
#pragma unroll
        for (int kk = 0; kk < 32; kk++) {
            float4 a0 = *(const float4*)&As[kk][tm*8];
            float4 a1 = *(const float4*)&As[kk][tm*8 + 4];
            ulonglong2 b01 = *(const ulonglong2*)&Ws[kk][tn*8];
            ulonglong2 b23 = *(const ulonglong2*)&Ws[kk][tn*8+4];
            unsigned long long av[8] = { pack2(a0.x, a0.x), pack2(a0.y, a0.y),
                                         pack2(a0.z, a0.z), pack2(a0.w, a0.w),
                                         pack2(a1.x, a1.x), pack2(a1.y, a1.y),
                                         pack2(a1.z, a1.z), pack2(a1.w, a1.w) };
#pragma unroll
            for (int i = 0; i < 8; i++) {
                ffma2(acc[i][0], av[i], b01.x);
                ffma2(acc[i][1], av[i], b01.y);
                ffma2(acc[i][2], av[i], b23.x);
                ffma2(acc[i][3], av[i], b23.y);
            }
        }
        __syncthreads();
    }

    float bia[8];
#pragma unroll
    for (int j = 0; j < 8; j++) bia[j] = bias ? bias[tn*8 + j] : 0.0f;

#pragma unroll
    for (int i = 0; i < 8; i++) {
        size_t row = (size_t)bm + tm*8 + i;
        float v[8];
#pragma unroll
        for (int j = 0; j < 4; j++) {
            float2 f = unpack2(acc[i][j]);
            v[2*j]   = f.x + bia[2*j];
            v[2*j+1] = f.y + bia[2*j+1];
        }
        float4* cp = (float4*)(C + row*128 + tn*8);
        cp[0] = make_float4(v[0], v[1], v[2], v[3]);
        cp[1] = make_float4(v[4], v[5], v[6], v[7]);
    }
}

// fc1 (and wqs/wks prep when gridDim.y==2 with W2/C2)
__global__ void __launch_bounds__(256, 2)
gemm_small(const float* __restrict__ A, int lda, int Ka,
           const float* __restrict__ W, const float* __restrict__ bias,
           float* __restrict__ C,
           const float* A2, const float* W2, float* C2) {
    if (blockIdx.y == 1) { A = A2; W = W2; C = C2; }
    gemm128_body(A, lda, Ka, W, bias, C, blockIdx.x * 128, threadIdx.x);
}

// batched 5-way: q,k,v,qs,ks all from x
struct Batch5 { const float* W[5]; float* C[5]; };
__global__ void __launch_bounds__(256, 2)
gemm_batch5(const float* __restrict__ A, Batch5 bt) {
    gemm128_body(A, DMf, DMf, bt.W[blockIdx.y], nullptr, bt.C[blockIdx.y],
                 blockIdx.x * 128, threadIdx.x);
}

// ---------------- mega kernel ----------------
#define OFF_AS  0
#define OFF_BS  (BROWS*PITCH)                    /* 8448  */
#define OFF_W   (2*BROWS*PITCH)                  /* 16896 */
#define OFF_QS  (OFF_W + 2*32*128)               /* 25088 */
#define OFF_SIM (OFF_QS + 512)                   /* 25600 */
#define OFF_QN  (OFF_SIM + 64)                   /* 25664 */
#define OFF_IDX (OFF_QN + 4)                     /* 25668 */
#define MEGA_FLOATS (OFF_IDX + 64)               /* 25732 -> 102928 B */

__device__ __forceinline__ void load_quarter(unsigned sW, const float* __restrict__ W,
                                             int quarter, int tid) {
    const float* src = W + (size_t)quarter*32*128;
#pragma unroll
    for (int it = 0; it < 4; it++) {
        int c = it*256 + tid;
        cpa16(sW + (unsigned)c*16u, src + c*4);
    }
}

__device__ __forceinline__ void mm32(const float* __restrict__ T, int kbase,
                                     const float* __restrict__ W,
                                     int tm, int tn,
                                     unsigned long long acc[4][4]) {
    const float* ap = T + tm*4*PITCH + kbase;
    const float* wp = W + tn*4;
#pragma unroll 4
    for (int kk = 0; kk < 32; kk += 2) {
        ulonglong2 B00 = *(const ulonglong2*)(wp + kk*128);
        ulonglong2 B01 = *(const ulonglong2*)(wp + kk*128 + 64);
        ulonglong2 B10 = *(const ulonglong2*)(wp + (kk+1)*128);
        ulonglong2 B11 = *(const ulonglong2*)(wp + (kk+1)*128 + 64);
#pragma unroll
        for (int i = 0; i < 4; i++) {
            float2 a = *(const float2*)(ap + i*PITCH + kk);
            unsigned long long av0 = pack2(a.x, a.x);
            unsigned long long av1 = pack2(a.y, a.y);
            ffma2(acc[i][0], av0, B00.x);
            ffma2(acc[i][1], av0, B00.y);
            ffma2(acc[i][2], av0, B01.x);
            ffma2(acc[i][3], av0, B01.y);
            ffma2(acc[i][0], av1, B10.x);
            ffma2(acc[i][1], av1, B10.y);
            ffma2(acc[i][2], av1, B11.x);
            ffma2(acc[i][3], av1, B11.y);
        }
    }
}

__global__ void __launch_bounds__(256, 2)
mega_kernel(const float* __restrict__ xyz,
            const float* __restrict__ d1_w, const float* __restrict__ d1_b,
            const float* __restrict__ d2_w, const float* __restrict__ d2_b,
            const float* __restrict__ sim_w, const float* __restrict__ sim_b,
            const float* __restrict__ g1_w, const float* __restrict__ g1_b,
            const float* __restrict__ g2_w, const float* __restrict__ g2_b,
            const float* __restrict__ fc2_w, const float* __restrict__ fc2_b,
            const float* __restrict__ features,
            float* __restrict__ out) {
    extern __shared__ float sm[];
    float* As   = sm + OFF_AS;     // h1 -> pe
    float* Bs   = sm + OFF_BS;     // t -> h2 -> softmax exchanges
    float* Wb   = sm + OFF_W;      // 2 x (32x128) ping-pong weight quarters
    float* Qs   = sm + OFF_QS;
    float* ssim = sm + OFF_SIM;
    float* sqn  = sm + OFF_QN;
    int*   sidx = (int*)(sm + OFF_IDX);
    unsigned sW = smem_u32(Wb);

    int tid  = threadIdx.x;
    int wid  = tid >> 5, lane = tid & 31;
    int tm   = tid >> 4, tn = tid & 15;
    int m0   = blockIdx.x * 4;
    size_t bm = (size_t)blockIdx.x * BROWS;
    int b    = m0 >> 12;

    const float* Wseq[3] = { d2_w, g1_w, g2_w };

    // prolog: group0 = quarter 0, group1 = quarter 1
    load_quarter(sW, Wseq[0], 0, tid);
    cpa_commit();
    load_quarter(sW + 4096u*4u, Wseq[0], 1, tid);
    cpa_commit();

    // ---- gather prologue ----
    if (tid < 64) sidx[tid] = g_idx[m0*KNN + tid];
    {
        float2 v = *(const float2*)(g_q + (size_t)m0*DMf + tid*2);
        *(float2*)(Qs + tid*2) = v;
    }
    __syncthreads();

    if (wid < 4) {
        float4 qf = *(const float4*)(Qs + wid*128 + lane*4);
        float s = qf.x*qf.x + qf.y*qf.y + qf.z*qf.z + qf.w*qf.w;
#pragma unroll
        for (int off = 16; off; off >>= 1) s += __shfl_xor_sync(0xffffffffu, s, off);
        if (lane == 0) sqn[wid] = fmaxf(sqrtf(s), EPSV);
    }
    __syncthreads();

    float4 w0 = *(const float4*)(d1_w + lane*4);
    float4 w1 = *(const float4*)(d1_w + 128 + lane*4);
    float4 w2 = *(const float4*)(d1_w + 256 + lane*4);
    float4 db = *(const float4*)(d1_b + lane*4);
    const float* xb = xyz + (size_t)b*NPTS*3;

#pragma unroll 1
    for (int it = 0; it < 8; it++) {
        int j   = it*8 + wid;
        int row = j >> 4;
        int n   = (m0 + row) & (NPTS - 1);
        int idx = sidx[j];

        float4 kf = *(const float4*)(g_kf + ((size_t)(b*NPTS + idx))*DMf + lane*4);
        float4 qf = *(const float4*)(Qs + row*128 + lane*4);
        float dq = qf.x*kf.x + qf.y*kf.y + qf.z*kf.z + qf.w*kf.w;
        float dk = kf.x*kf.x + kf.y*kf.y + kf.z*kf.z + kf.w*kf.w;
#pragma unroll
        for (int off = 16; off; off >>= 1) {
            dq += __shfl_xor_sync(0xffffffffu, dq, off);
            dk += __shfl_xor_sync(0xffffffffu, dk, off);
        }
        float kn = fmaxf(sqrtf(dk), EPSV);
        if (lane == 0) ssim[j] = dq / (sqn[row] * kn);

        float cx = xb[n*3+0] - xb[idx*3+0];
        float cy = xb[n*3+1] - xb[idx*3+1];
        float cz = xb[n*3+2] - xb[idx*3+2];
        float4 h;
        h.x = fmaxf(cx*w0.x + cy*w1.x + cz*w2.x + db.x, 0.0f);
        h.y = fmaxf(cx*w0.y + cy*w1.y + cz*w2.y + db.y, 0.0f);
        h.z = fmaxf(cx*w0.z + cy*w1.z + cz*w2.z + db.z, 0.0f);
        h.w = fmaxf(cx*w0.w + cy*w1.w + cz*w2.w + db.w, 0.0f);
        *(float4*)(As + j*PITCH + lane*4) = h;
    }

    // ---- 3-GEMM chain (R10-style two-buffer distance-2 prefetch) ----
    unsigned long long acc[4][4];
#pragma unroll
    for (int i = 0; i < 4; i++)
#pragma unroll
        for (int j = 0; j < 4; j++) acc[i][j] = 0ULL;

    int ch = 0;
    for (int g = 0; g < 3; g++) {
        if (g >= 1) {
#pragma unroll
            for (int i = 0; i < 4; i++)
#pragma unroll
                for (int j = 0; j < 4; j++) acc[i][j] = 0ULL;
        }
        const float* tile = (g == 0) ? As : Bs;
        for (int q = 0; q < 4; q++) {
            if (ch < 11) cpa_wait<1>(); else cpa_wait<0>();
            __syncthreads();
            mm32(tile, q*32, Wb + (ch & 1)*4096, tm, tn, acc);
            __syncthreads();
            int nxt = ch + 2;
            if (nxt < 12) {
                load_quarter(sW + (unsigned)((nxt & 1)*4096)*4u, Wseq[nxt >> 2], nxt & 3, tid);
                cpa_commit();
            }
            ch++;
        }

        if (g == 0) {
            // epi1: pe = acc + d2_b -> As ; t = pe + qs[m] - ks[idx] + sim*sw0 + sim_b -> Bs
            float4 b0 = *(const float4*)(d2_b + tn*4);
            float4 b1 = *(const float4*)(d2_b + 64 + tn*4);
            float4 sb0 = *(const float4*)(sim_b + tn*4);
            float4 sb1 = *(const float4*)(sim_b + 64 + tn*4);
            float4 s0 = *(const float4*)(sim_w + tn*4);
            float4 s1 = *(const float4*)(sim_w + 64 + tn*4);
            float bb[8]  = {b0.x,b0.y,b0.z,b0.w,b1.x,b1.y,b1.z,b1.w};
            float sbb[8] = {sb0.x,sb0.y,sb0.z,sb0.w,sb1.x,sb1.y,sb1.z,sb1.w};
            float sw[8]  = {s0.x,s0.y,s0.z,s0.w,s1.x,s1.y,s1.z,s1.w};
#pragma unroll
            for (int i = 0; i < 4; i++) {
                int r = tm*4 + i;
                float sv = ssim[r];
                const float* qsp = g_qs + (size_t)(m0 + (r >> 4))*DMf;
                const float* ksp = g_ks + ((size_t)(b*NPTS + sidx[r]))*DMf;
                float4 q0 = *(const float4*)(qsp + tn*4);
                float4 q1 = *(const float4*)(qsp + 64 + tn*4);
                float4 k0 = *(const float4*)(ksp + tn*4);
                float4 k1 = *(const float4*)(ksp + 64 + tn*4);
                float qs8[8] = {q0.x,q0.y,q0.z,q0.w,q1.x,q1.y,q1.z,q1.w};
                float ks8[8] = {k0.x,k0.y,k0.z,k0.w,k1.x,k1.y,k1.z,k1.w};
                float pe[8], t[8];
#pragma unroll
                for (int j = 0; j < 4; j++) {
                    float2 f = unpack2(acc[i][j]);
                    pe[2*j]   = f.x + bb[2*j];
                    pe[2*j+1] = f.y + bb[2*j+1];
                }
#pragma unroll
                for (int s = 0; s < 8; s++)
                    t[s] = pe[s] + qs8[s] - ks8[s] + sv*sw[s] + sbb[s];
                *(float4*)&As[r*PITCH + tn*4]      = make_float4(pe[0],pe[1],pe[2],pe[3]);
                *(float4*)&As[r*PITCH + 64 + tn*4] = make_float4(pe[4],pe[5],pe[6],pe[7]);
                *(float4*)&Bs[r*PITCH + tn*4]      = make_float4(t[0],t[1],t[2],t[3]);
                *(float4*)&Bs[r*PITCH + 64 + tn*4] = make_float4(t[4],t[5],t[6],t[7]);
            }
            __syncthreads();
        } else if (g == 1) {
            // epi2: relu(+g1_b); h2 -> Bs
            float4 b0 = *(const float4*)(g1_b + tn*4);
            float4 b1 = *(const float4*)(g1_b + 64 + tn*4);
            float bb[8] = {b0.x,b0.y,b0.z,b0.w,b1.x,b1.y,b1.z,b1.w};
#pragma unroll
            for (int i = 0; i < 4; i++) {
                int r = tm*4 + i;
                float v[8];
#pragma unroll
                for (int j = 0; j < 4; j++) {
                    float2 f = unpack2(acc[i][j]);
                    v[2*j]   = fmaxf(f.x + bb[2*j],   0.0f);
                    v[2*j+1] = fmaxf(f.y + bb[2*j+1], 0.0f);
                }
                *(float4*)&Bs[r*PITCH + tn*4]      = make_float4(v[0],v[1],v[2],v[3]);
                *(float4*)&Bs[r*PITCH + 64 + tn*4] = make_float4(v[4],v[5],v[6],v[7]);
            }
            __syncthreads();
        }
    }
    __syncthreads();

    // ---- epilogue: softmax(k) + attn out + weighted sum + fc2 + residual ----
    {
        const float scale = 0.08838834764831845f;   // 1/sqrt(128)
        int q = tm >> 2;
        int mb = q*4;

        float sc[4][8];
        {
            float4 b0 = *(const float4*)(g2_b + tn*4);
            float4 b1 = *(const float4*)(g2_b + 64 + tn*4);
            float bb[8] = {b0.x,b0.y,b0.z,b0.w,b1.x,b1.y,b1.z,b1.w};
#pragma unroll
            for (int i = 0; i < 4; i++)
#pragma unroll
                for (int j = 0; j < 4; j++) {
                    float2 f = unpack2(acc[i][j]);
                    sc[i][2*j]   = (f.x + bb[2*j])   * scale;
                    sc[i][2*j+1] = (f.y + bb[2*j+1]) * scale;
                }
        }
        {
            float m4[8];
#pragma unroll
            for (int s = 0; s < 8; s++)
                m4[s] = fmaxf(fmaxf(sc[0][s], sc[1][s]), fmaxf(sc[2][s], sc[3][s]));
            *(float4*)&Bs[tm*128 + tn*4]      = make_float4(m4[0],m4[1],m4[2],m4[3]);
            *(float4*)&Bs[tm*128 + 64 + tn*4] = make_float4(m4[4],m4[5],m4[6],m4[7]);
        }
        __syncthreads();
        float mx[8];
#pragma unroll
        for (int s = 0; s < 8; s++) {
            int col = (s < 4) ? tn*4 + s : 64 + tn*4 + (s-4);
            float a0 = Bs[(mb+0)*128 + col];
            float a1 = Bs[(mb+1)*128 + col];
            float a2 = Bs[(mb+2)*128 + col];
            float a3 = Bs[(mb+3)*128 + col];
            mx[s] = fmaxf(fmaxf(a0,a1), fmaxf(a2,a3));
        }
        float e[4][8], ps[8];
#pragma unroll
        for (int s = 0; s < 8; s++) {
            float p = 0.0f;
#pragma unroll
            for (int i = 0; i < 4; i++) { e[i][s] = expf(sc[i][s] - mx[s]); p += e[i][s]; }
            ps[s] = p;
        }
        *(float4*)&Bs[2048 + tm*128 + tn*4]      = make_float4(ps[0],ps[1],ps[2],ps[3]);
        *(float4*)&Bs[2048 + tm*128 + 64 + tn*4] = make_float4(ps[4],ps[5],ps[6],ps[7]);
        __syncthreads();
        float inv[8];
#pragma unroll
        for (int s = 0; s < 8; s++) {
            int col = (s < 4) ? tn*4 + s : 64 + tn*4 + (s-4);
            float su = Bs[2048 + (mb+0)*128 + col] + Bs[2048 + (mb+1)*128 + col]
                     + Bs[2048 + (mb+2)*128 + col] + Bs[2048 + (mb+3)*128 + col];
            inv[s] = 1.0f / su;
        }

        float pr[8];
#pragma unroll
        for (int s = 0; s < 8; s++) pr[s] = 0.0f;
        float* outA = out + (size_t)M1*DPf;
#pragma unroll
        for (int i = 0; i < 4; i++) {
            int r = tm*4 + i;
            const float* vp = g_vf + ((size_t)(b*NPTS + sidx[r]))*DMf;
            float a0 = e[i][0]*inv[0], a1 = e[i][1]*inv[1],
                  a2 = e[i][2]*inv[2], a3 = e[i][3]*inv[3];
            float a4 = e[i][4]*inv[4], a5 = e[i][5]*inv[5],
                  a6 = e[i][6]*inv[6], a7 = e[i][7]*inv[7];
            float4 v0 = *(const float4*)(vp + tn*4);
            float4 v1 = *(const float4*)(vp + 64 + tn*4);
            float4 p0 = *(const float4*)&As[r*PITCH + tn*4];
            float4 p1 = *(const float4*)&As[r*PITCH + 64 + tn*4];
            *(float4*)(outA + (bm + r)*128 + tn*4)      = make_float4(a0,a1,a2,a3);
            *(float4*)(outA + (bm + r)*128 + 64 + tn*4) = make_float4(a4,a5,a6,a7);
            pr[0] += a0*(v0.x+p0.x); pr[1] += a1*(v0.y+p0.y);
            pr[2] += a2*(v0.z+p0.z); pr[3] += a3*(v0.w+p0.w);
            pr[4] += a4*(v1.x+p1.x); pr[5] += a5*(v1.y+p1.y);
            pr[6] += a6*(v1.z+p1.z); pr[7] += a7*(v1.w+p1.w);
        }
        __syncthreads();
        *(float4*)&Bs[tm*128 + tn*4]      = make_float4(pr[0],pr[1],pr[2],pr[3]);
        *(float4*)&Bs[tm*128 + 64 + tn*4] = make_float4(pr[4],pr[5],pr[6],pr[7]);
        __syncthreads();

#pragma unroll
        for (int rep = 0; rep < 2; rep++) {
            int ii  = rep*256 + tid;
            int qq  = ii >> 7;
            int col = ii & 127;
            As[qq*128 + col] = Bs[(qq*4+0)*128 + col] + Bs[(qq*4+1)*128 + col]
                             + Bs[(qq*4+2)*128 + col] + Bs[(qq*4+3)*128 + col];
        }
        __syncthreads();

        {
            int qf = tid >> 6, f = tid & 63;
            const float* rp = As + qf*128;
            float o0 = 0.f, o1 = 0.f, o2 = 0.f, o3 = 0.f;
#pragma unroll 8
            for (int j = 0; j < 128; j += 4) {
                o0 += rp[j]   * fc2_w[ j   *DPf + f];
                o1 += rp[j+1] * fc2_w[(j+1)*DPf + f];
                o2 += rp[j+2] * fc2_w[(j+2)*DPf + f];
                o3 += rp[j+3] * fc2_w[(j+3)*DPf + f];
            }
            float o = fc2_b[f] + ((o0 + o1) + (o2 + o3))
                    + features[(size_t)(m0 + qf)*DPf + f];
            out[(size_t)(m0 + qf)*DPf + f] = o;
        }
    }
}

// ---------------- launch ----------------
extern "C" void kernel_launch(void* const* d_in, const int* in_sizes, int n_in,
                              void* d_out, int out_size) {
    const float* xyz   = (const float*)d_in[0];
    const float* feat  = (const float*)d_in[1];
    const float* fc1_w = (const float*)d_in[2];
    const float* fc1_b = (const float*)d_in[3];
    const float* fc2_w = (const float*)d_in[4];
    const float* fc2_b = (const float*)d_in[5];
    const float* d1_w  = (const float*)d_in[6];
    const float* d1_b  = (const float*)d_in[7];
    const float* d2_w  = (const float*)d_in[8];
    const float* d2_b  = (const float*)d_in[9];
    const float* g1_w  = (const float*)d_in[10];
    const float* g1_b  = (const float*)d_in[11];
    const float* g2_w  = (const float*)d_in[12];
    const float* g2_b  = (const float*)d_in[13];
    const float* wq_w  = (const float*)d_in[14];
    const float* wk_w  = (const float*)d_in[15];
    const float* wv_w  = (const float*)d_in[16];
    const float* sim_w = (const float*)d_in[17];
    const float* sim_b = (const float*)d_in[18];
    float* out = (float*)d_out;

    static float *p_x = nullptr, *p_q, *p_kf, *p_vf, *p_qs, *p_ks, *p_wqs, *p_wks;
    static bool attr_done = false;
    const int MEGA_SMEM = MEGA_FLOATS * 4;   // 102928 B
    if (!attr_done) {
        cudaGetSymbolAddress((void**)&p_x,   g_x);
        cudaGetSymbolAddress((void**)&p_q,   g_q);
        cudaGetSymbolAddress((void**)&p_kf,  g_kf);
        cudaGetSymbolAddress((void**)&p_vf,  g_vf);
        cudaGetSymbolAddress((void**)&p_qs,  g_qs);
        cudaGetSymbolAddress((void**)&p_ks,  g_ks);
        cudaGetSymbolAddress((void**)&p_wqs, g_wqs);
        cudaGetSymbolAddress((void**)&p_wks, g_wks);
        cudaFuncSetAttribute(mega_kernel,
                             cudaFuncAttributeMaxDynamicSharedMemorySize, MEGA_SMEM);
        attr_done = true;
    }

    // 0) KNN
    knn_kernel<<<M1/4, 128>>>(xyz);

    // 0b) combined weights: wqs = wq@simw', wks = wk@simw'  (grid (1,2))
    gemm_small<<<dim3(1, 2), 256>>>(wq_w, DMf, DMf, sim_w + 128, nullptr, p_wqs,
                                    wk_w, sim_w + 128, p_wks);

    // 1) x = features @ fc1 + b
    gemm_small<<<M1/128, 256>>>(feat, DPf, DPf, fc1_w, fc1_b, p_x,
                                nullptr, nullptr, nullptr);

    // 2) q, k, v, qs, ks  (one batched launch from x)
    Batch5 bt;
    bt.W[0] = wq_w;  bt.C[0] = p_q;
    bt.W[1] = wk_w;  bt.C[1] = p_kf;
    bt.W[2] = wv_w;  bt.C[2] = p_vf;
    bt.W[3] = p_wqs; bt.C[3] = p_qs;
    bt.W[4] = p_wks; bt.C[4] = p_ks;
    gemm_batch5<<<dim3(M1/128, 5), 256>>>(p_x, bt);

    // 3) mega
    mega_kernel<<<M1/4, 256, MEGA_SMEM>>>(xyz, d1_w, d1_b, d2_w, d2_b,
                                          sim_w, sim_b, g1_w, g1_b, g2_w, g2_b,
                                          fc2_w, fc2_b, feat, out);
}

// round 14
// speedup vs baseline: 1.0758x; 1.0277x over previous
#include <cuda_runtime.h>
#include <math.h>

#define NB 4
#define NPTS 4096
#define KNN 16
#define DPf 64
#define DMf 128
#define M1 (NB*NPTS)          /* 16384  */
#define M2 (M1*KNN)           /* 262144 */
#define EPSV 1e-8f
#define PITCH 132             /* smem tile pitch; 4*132=528 words, %32=16 -> conflict-free */
#define BROWS 64

// ---------------- scratch ----------------
__device__ float g_x [(size_t)M1*DMf];
__device__ float g_q [(size_t)M1*DMf];
__device__ float g_kf[(size_t)M1*DMf];
__device__ float g_vf[(size_t)M1*DMf];
__device__ float g_qs[(size_t)M1*DMf];   // x @ (wq@simw')
__device__ float g_ks[(size_t)M1*DMf];   // x @ (wk@simw')
__device__ float g_wqs[DMf*DMf];         // wq @ simw'
__device__ float g_wks[DMf*DMf];         // wk @ simw'
__device__ int   g_idx[M1*KNN];

// ---------------- packed f32x2 helpers ----------------
__device__ __forceinline__ unsigned long long pack2(float x, float y) {
    unsigned long long r;
    asm("mov.b64 %0, {%1, %2};" : "=l"(r) : "f"(x), "f"(y));
    return r;
}
__device__ __forceinline__ float2 unpack2(unsigned long long v) {
    float2 f;
    asm("mov.b64 {%0, %1}, %2;" : "=f"(f.x), "=f"(f.y) : "l"(v));
    return f;
}
__device__ __forceinline__ void ffma2(unsigned long long& d,
                                      unsigned long long a,
                                      unsigned long long b) {
    asm("fma.rn.f32x2 %0, %1, %2, %0;" : "+l"(d) : "l"(a), "l"(b));
}

// ---------------- cp.async helpers ----------------
__device__ __forceinline__ unsigned smem_u32(const void* p) {
    unsigned a;
    asm("{ .reg .u64 t; cvta.to.shared.u64 t, %1; cvt.u32.u64 %0, t; }" : "=r"(a) : "l"(p));
    return a;
}
__device__ __forceinline__ void cpa16(unsigned dst, const void* src) {
    asm volatile("cp.async.ca.shared.global [%0], [%1], 16;" :: "r"(dst), "l"(src));
}
__device__ __forceinline__ void cpa_commit() { asm volatile("cp.async.commit_group;"); }
template<int N> __device__ __forceinline__ void cpa_wait() {
    asm volatile("cp.async.wait_group %0;" :: "n"(N));
}

// ---------------- KNN: warp per query, branchless register top-16 (R10 version) ------
__global__ void knn_kernel(const float* __restrict__ xyz) {
    int warp = threadIdx.x >> 5;
    int lane = threadIdx.x & 31;
    int row  = blockIdx.x * 4 + warp;
    int b = row >> 12;
    int n = row & (NPTS - 1);
    const float* xb = xyz + (size_t)b * NPTS * 3;
    float qx = xb[n*3+0], qy = xb[n*3+1], qz = xb[n*3+2];
    float sq = qx*qx + qy*qy + qz*qz;

    unsigned long long best[16];
#pragma unroll
    for (int i = 0; i < 16; i++) best[i] = ~0ULL;

    for (int t = 0; t < NPTS/32; t++) {
        int j = t*32 + lane;
        float x = xb[j*3+0], y = xb[j*3+1], z = xb[j*3+2];
        float sj = x*x + y*y + z*z;
        float d = sq + sj - 2.0f*(qx*x + qy*y + qz*z);
        unsigned u = __float_as_uint(d);
        u = (u & 0x80000000u) ? ~u : (u | 0x80000000u);
        unsigned long long key = ((unsigned long long)u << 32) | (unsigned)j;

        bool pi = key < best[15];
#pragma unroll
        for (int i = 15; i >= 1; i--) {
            bool pim = key < best[i-1];
            best[i] = pi ? (pim ? best[i-1] : key) : best[i];
            pi = pim;
        }
        best[0] = pi ? key : best[0];
    }

    __shared__ unsigned long long sh[4][512];
#pragma unroll
    for (int i = 0; i < 16; i++) sh[warp][lane*16 + i] = best[i];
    __syncwarp();

    int p = 0;
    for (int r = 0; r < 16; r++) {
        unsigned long long v = (p < 16) ? sh[warp][lane*16 + p] : ~0ULL;
        unsigned long long m = v;
#pragma unroll
        for (int off = 16; off; off >>= 1) {
            unsigned long long o = __shfl_xor_sync(0xffffffffu, m, off);
            m = (o < m) ? o : m;
        }
        if (v == m) { g_idx[row*KNN + r] = (int)(m & 0xffffffffu); p++; }
        __syncwarp();
    }
}

// ---------------- GEMM core (shared by variants) ----------------
__device__ __forceinline__ void gemm128_body(const float* __restrict__ A, int lda, int Ka,
                                             const float* __restrict__ W,
                                             const float* __restrict__ bias,
                                             float* __restrict__ C, int bm, int tid) {
    __shared__ float As[32][132];
    __shared__ float Ws[32][128];
    int tm = tid >> 4, tn = tid & 15;

    unsigned long long acc[8][4];
#pragma unroll
    for (int i = 0; i < 8; i++)
#pragma unroll
        for (int j = 0; j < 4; j++) acc[i][j] = 0ULL;

    for (int k0 = 0; k0 < Ka; k0 += 32) {
#pragma unroll
        for (int pss = 0; pss < 4; pss++) {
            int idx4 = pss*256 + tid;
            int r  = idx4 >> 3;
            int c4 = idx4 & 7;
            float4 v = *(const float4*)(A + (size_t)(bm + r)*lda + k0 + c4*4);
            As[c4*4+0][r] = v.x; As[c4*4+1][r] = v.y;
            As[c4*4+2][r] = v.z; As[c4*4+3][r] = v.w;
        }
#pragma unroll
        for (int pss = 0; pss < 4; pss++) {
            int idx4 = pss*256 + tid;
            int r  = idx4 >> 5;
            int c4 = idx4 & 31;
            *(float4*)&Ws[r][c4*4] = *(const float4*)(W + (size_t)(k0 + r)*128 + c4*4);
        }
        __syncthreads();
#pragma unroll
        for (int kk = 0; kk < 32; kk++) {
            float4 a0 = *(const float4*)&As[kk][tm*8];
            float4 a1 = *(const float4*)&As[kk][tm*8 + 4];
            ulonglong2 b01 = *(const ulonglong2*)&Ws[kk][tn*8];
            ulonglong2 b23 = *(const ulonglong2*)&Ws[kk][tn*8+4];
            unsigned long long av[8] = { pack2(a0.x, a0.x), pack2(a0.y, a0.y),
                                         pack2(a0.z, a0.z), pack2(a0.w, a0.w),
                                         pack2(a1.x, a1.x), pack2(a1.y, a1.y),
                                         pack2(a1.z, a1.z), pack2(a1.w, a1.w) };
#pragma unroll
            for (int i = 0; i < 8; i++) {
                ffma2(acc[i][0], av[i], b01.x);
                ffma2(acc[i][1], av[i], b01.y);
                ffma2(acc[i][2], av[i], b23.x);
                ffma2(acc[i][3], av[i], b23.y);
            }
        }
        __syncthreads();
    }

    float bia[8];
#pragma unroll
    for (int j = 0; j < 8; j++) bia[j] = bias ? bias[tn*8 + j] : 0.0f;

#pragma unroll
    for (int i = 0; i < 8; i++) {
        size_t row = (size_t)bm + tm*8 + i;
        float v[8];
#pragma unroll
        for (int j = 0; j < 4; j++) {
            float2 f = unpack2(acc[i][j]);
            v[2*j]   = f.x + bia[2*j];
            v[2*j+1] = f.y + bia[2*j+1];
        }
        float4* cp = (float4*)(C + row*128 + tn*8);
        cp[0] = make_float4(v[0], v[1], v[2], v[3]);
        cp[1] = make_float4(v[4], v[5], v[6], v[7]);
    }
}

// fc1 (and wqs/wks prep when gridDim.y==2 with W2/C2)
__global__ void __launch_bounds__(256, 2)
gemm_small(const float* __restrict__ A, int lda, int Ka,
           const float* __restrict__ W, const float* __restrict__ bias,
           float* __restrict__ C,
           const float* A2, const float* W2, float* C2) {
    if (blockIdx.y == 1) { A = A2; W = W2; C = C2; }
    gemm128_body(A, lda, Ka, W, bias, C, blockIdx.x * 128, threadIdx.x);
}

// batched 5-way: q,k,v,qs,ks all from x
struct Batch5 { const float* W[5]; float* C[5]; };
__global__ void __launch_bounds__(256, 2)
gemm_batch5(const float* __restrict__ A, Batch5 bt) {
    gemm128_body(A, DMf, DMf, bt.W[blockIdx.y], nullptr, bt.C[blockIdx.y],
                 blockIdx.x * 128, threadIdx.x);
}

// ---------------- mega kernel ----------------
#define OFF_AS  0
#define OFF_BS  (BROWS*PITCH)                    /* 8448  */
#define OFF_W   (2*BROWS*PITCH)                  /* 16896 */
#define OFF_QS  (OFF_W + 2*32*128)               /* 25088 */
#define OFF_SIM (OFF_QS + 512)                   /* 25600 */
#define OFF_QN  (OFF_SIM + 64)                   /* 25664 */
#define OFF_IDX (OFF_QN + 4)                     /* 25668 */
#define MEGA_FLOATS (OFF_IDX + 64)               /* 25732 -> 102928 B */

__device__ __forceinline__ void load_quarter(unsigned sW, const float* __restrict__ W,
                                             int quarter, int tid) {
    const float* src = W + (size_t)quarter*32*128;
#pragma unroll
    for (int it = 0; it < 4; it++) {
        int c = it*256 + tid;
        cpa16(sW + (unsigned)c*16u, src + c*4);
    }
}

__device__ __forceinline__ void mm32(const float* __restrict__ T, int kbase,
                                     const float* __restrict__ W,
                                     int tm, int tn,
                                     unsigned long long acc[4][4]) {
    const float* ap = T + tm*4*PITCH + kbase;
    const float* wp = W + tn*4;
#pragma unroll 4
    for (int kk = 0; kk < 32; kk += 2) {
        ulonglong2 B00 = *(const ulonglong2*)(wp + kk*128);
        ulonglong2 B01 = *(const ulonglong2*)(wp + kk*128 + 64);
        ulonglong2 B10 = *(const ulonglong2*)(wp + (kk+1)*128);
        ulonglong2 B11 = *(const ulonglong2*)(wp + (kk+1)*128 + 64);
#pragma unroll
        for (int i = 0; i < 4; i++) {
            float2 a = *(const float2*)(ap + i*PITCH + kk);
            unsigned long long av0 = pack2(a.x, a.x);
            unsigned long long av1 = pack2(a.y, a.y);
            ffma2(acc[i][0], av0, B00.x);
            ffma2(acc[i][1], av0, B00.y);
            ffma2(acc[i][2], av0, B01.x);
            ffma2(acc[i][3], av0, B01.y);
            ffma2(acc[i][0], av1, B10.x);
            ffma2(acc[i][1], av1, B10.y);
            ffma2(acc[i][2], av1, B11.x);
            ffma2(acc[i][3], av1, B11.y);
        }
    }
}

__global__ void __launch_bounds__(256, 2)
mega_kernel(const float* __restrict__ xyz,
            const float* __restrict__ d1_w, const float* __restrict__ d1_b,
            const float* __restrict__ d2_w, const float* __restrict__ d2_b,
            const float* __restrict__ sim_w, const float* __restrict__ sim_b,
            const float* __restrict__ g1_w, const float* __restrict__ g1_b,
            const float* __restrict__ g2_w, const float* __restrict__ g2_b,
            const float* __restrict__ fc2_w, const float* __restrict__ fc2_b,
            const float* __restrict__ features,
            float* __restrict__ out) {
    extern __shared__ float sm[];
    float* As   = sm + OFF_AS;     // h1 -> pe
    float* Bs   = sm + OFF_BS;     // t -> h2 -> softmax exchanges
    float* Wb   = sm + OFF_W;      // 2 x (32x128) ping-pong weight quarters
    float* Qs   = sm + OFF_QS;
    float* ssim = sm + OFF_SIM;
    float* sqn  = sm + OFF_QN;
    int*   sidx = (int*)(sm + OFF_IDX);
    unsigned sW = smem_u32(Wb);

    int tid  = threadIdx.x;
    int wid  = tid >> 5, lane = tid & 31;
    int tm   = tid >> 4, tn = tid & 15;
    int m0   = blockIdx.x * 4;
    size_t bm = (size_t)blockIdx.x * BROWS;
    int b    = m0 >> 12;

    const float* Wseq[3] = { d2_w, g1_w, g2_w };

    // prolog: group0 = quarter 0, group1 = quarter 1
    load_quarter(sW, Wseq[0], 0, tid);
    cpa_commit();
    load_quarter(sW + 4096u*4u, Wseq[0], 1, tid);
    cpa_commit();

    // ---- gather prologue ----
    if (tid < 64) sidx[tid] = g_idx[m0*KNN + tid];
    {
        float2 v = *(const float2*)(g_q + (size_t)m0*DMf + tid*2);
        *(float2*)(Qs + tid*2) = v;
    }
    __syncthreads();

    if (wid < 4) {
        float4 qf = *(const float4*)(Qs + wid*128 + lane*4);
        float s = qf.x*qf.x + qf.y*qf.y + qf.z*qf.z + qf.w*qf.w;
#pragma unroll
        for (int off = 16; off; off >>= 1) s += __shfl_xor_sync(0xffffffffu, s, off);
        if (lane == 0) sqn[wid] = fmaxf(sqrtf(s), EPSV);
    }
    __syncthreads();

    float4 w0 = *(const float4*)(d1_w + lane*4);
    float4 w1 = *(const float4*)(d1_w + 128 + lane*4);
    float4 w2 = *(const float4*)(d1_w + 256 + lane*4);
    float4 db = *(const float4*)(d1_b + lane*4);
    const float* xb = xyz + (size_t)b*NPTS*3;

#pragma unroll 1
    for (int it = 0; it < 8; it++) {
        int j   = it*8 + wid;
        int row = j >> 4;
        int n   = (m0 + row) & (NPTS - 1);
        int idx = sidx[j];

        float4 kf = *(const float4*)(g_kf + ((size_t)(b*NPTS + idx))*DMf + lane*4);
        float4 qf = *(const float4*)(Qs + row*128 + lane*4);
        float dq = qf.x*kf.x + qf.y*kf.y + qf.z*kf.z + qf.w*kf.w;
        float dk = kf.x*kf.x + kf.y*kf.y + kf.z*kf.z + kf.w*kf.w;
#pragma unroll
        for (int off = 16; off; off >>= 1) {
            dq += __shfl_xor_sync(0xffffffffu, dq, off);
            dk += __shfl_xor_sync(0xffffffffu, dk, off);
        }
        float kn = fmaxf(sqrtf(dk), EPSV);
        if (lane == 0) ssim[j] = dq / (sqn[row] * kn);

        float cx = xb[n*3+0] - xb[idx*3+0];
        float cy = xb[n*3+1] - xb[idx*3+1];
        float cz = xb[n*3+2] - xb[idx*3+2];
        float4 h;
        h.x = fmaxf(cx*w0.x + cy*w1.x + cz*w2.x + db.x, 0.0f);
        h.y = fmaxf(cx*w0.y + cy*w1.y + cz*w2.y + db.y, 0.0f);
        h.z = fmaxf(cx*w0.z + cy*w1.z + cz*w2.z + db.z, 0.0f);
        h.w = fmaxf(cx*w0.w + cy*w1.w + cz*w2.w + db.w, 0.0f);
        *(float4*)(As + j*PITCH + lane*4) = h;
    }

    // ---- 3-GEMM chain (two-buffer distance-2 prefetch) ----
    unsigned long long acc[4][4];
#pragma unroll
    for (int i = 0; i < 4; i++)
#pragma unroll
        for (int j = 0; j < 4; j++) acc[i][j] = 0ULL;

    int ch = 0;
    for (int g = 0; g < 3; g++) {
        if (g >= 1) {
#pragma unroll
            for (int i = 0; i < 4; i++)
#pragma unroll
                for (int j = 0; j < 4; j++) acc[i][j] = 0ULL;
        }
        const float* tile = (g == 0) ? As : Bs;
        for (int q = 0; q < 4; q++) {
            if (ch < 11) cpa_wait<1>(); else cpa_wait<0>();
            __syncthreads();
            mm32(tile, q*32, Wb + (ch & 1)*4096, tm, tn, acc);
            __syncthreads();
            int nxt = ch + 2;
            if (nxt < 12) {
                load_quarter(sW + (unsigned)((nxt & 1)*4096)*4u, Wseq[nxt >> 2], nxt & 3, tid);
                cpa_commit();
            }
            ch++;
        }

        if (g == 0) {
            // epi1: pe = acc + d2_b -> As ; t = pe + qs[m] - ks[idx] + sim*sw0 + sim_b -> Bs
            float4 b0 = *(const float4*)(d2_b + tn*4);
            float4 b1 = *(const float4*)(d2_b + 64 + tn*4);
            float4 sb0 = *(const float4*)(sim_b + tn*4);
            float4 sb1 = *(const float4*)(sim_b + 64 + tn*4);
            float4 s0 = *(const float4*)(sim_w + tn*4);
            float4 s1 = *(const float4*)(sim_w + 64 + tn*4);
            float bb[8]  = {b0.x,b0.y,b0.z,b0.w,b1.x,b1.y,b1.z,b1.w};
            float sbb[8] = {sb0.x,sb0.y,sb0.z,sb0.w,sb1.x,sb1.y,sb1.z,sb1.w};
            float sw[8]  = {s0.x,s0.y,s0.z,s0.w,s1.x,s1.y,s1.z,s1.w};
#pragma unroll
            for (int i = 0; i < 4; i++) {
                int r = tm*4 + i;
                float sv = ssim[r];
                const float* qsp = g_qs + (size_t)(m0 + (r >> 4))*DMf;
                const float* ksp = g_ks + ((size_t)(b*NPTS + sidx[r]))*DMf;
                float4 q0 = *(const float4*)(qsp + tn*4);
                float4 q1 = *(const float4*)(qsp + 64 + tn*4);
                float4 k0 = *(const float4*)(ksp + tn*4);
                float4 k1 = *(const float4*)(ksp + 64 + tn*4);
                float qs8[8] = {q0.x,q0.y,q0.z,q0.w,q1.x,q1.y,q1.z,q1.w};
                float ks8[8] = {k0.x,k0.y,k0.z,k0.w,k1.x,k1.y,k1.z,k1.w};
                float pe[8], t[8];
#pragma unroll
                for (int j = 0; j < 4; j++) {
                    float2 f = unpack2(acc[i][j]);
                    pe[2*j]   = f.x + bb[2*j];
                    pe[2*j+1] = f.y + bb[2*j+1];
                }
#pragma unroll
                for (int s = 0; s < 8; s++)
                    t[s] = pe[s] + qs8[s] - ks8[s] + sv*sw[s] + sbb[s];
                *(float4*)&As[r*PITCH + tn*4]      = make_float4(pe[0],pe[1],pe[2],pe[3]);
                *(float4*)&As[r*PITCH + 64 + tn*4] = make_float4(pe[4],pe[5],pe[6],pe[7]);
                *(float4*)&Bs[r*PITCH + tn*4]      = make_float4(t[0],t[1],t[2],t[3]);
                *(float4*)&Bs[r*PITCH + 64 + tn*4] = make_float4(t[4],t[5],t[6],t[7]);
            }
            __syncthreads();
        } else if (g == 1) {
            // epi2: relu(+g1_b); h2 -> Bs
            float4 b0 = *(const float4*)(g1_b + tn*4);
            float4 b1 = *(const float4*)(g1_b + 64 + tn*4);
            float bb[8] = {b0.x,b0.y,b0.z,b0.w,b1.x,b1.y,b1.z,b1.w};
#pragma unroll
            for (int i = 0; i < 4; i++) {
                int r = tm*4 + i;
                float v[8];
#pragma unroll
                for (int j = 0; j < 4; j++) {
                    float2 f = unpack2(acc[i][j]);
                    v[2*j]   = fmaxf(f.x + bb[2*j],   0.0f);
                    v[2*j+1] = fmaxf(f.y + bb[2*j+1], 0.0f);
                }
                *(float4*)&Bs[r*PITCH + tn*4]      = make_float4(v[0],v[1],v[2],v[3]);
                *(float4*)&Bs[r*PITCH + 64 + tn*4] = make_float4(v[4],v[5],v[6],v[7]);
            }
            __syncthreads();
        }
    }
    __syncthreads();

    // ---- epilogue: softmax(k) + attn out + weighted sum + fc2 + residual ----
    {
        const float scale = 0.08838834764831845f;   // 1/sqrt(128)
        int q = tm >> 2;
        int mb = q*4;

        float sc[4][8];
        {
            float4 b0 = *(const float4*)(g2_b + tn*4);
            float4 b1 = *(const float4*)(g2_b + 64 + tn*4);
            float bb[8] = {b0.x,b0.y,b0.z,b0.w,b1.x,b1.y,b1.z,b1.w};
#pragma unroll
            for (int i = 0; i < 4; i++)
#pragma unroll
                for (int j = 0; j < 4; j++) {
                    float2 f = unpack2(acc[i][j]);
                    sc[i][2*j]   = (f.x + bb[2*j])   * scale;
                    sc[i][2*j+1] = (f.y + bb[2*j+1]) * scale;
                }
        }
        {
            float m4[8];
#pragma unroll
            for (int s = 0; s < 8; s++)
                m4[s] = fmaxf(fmaxf(sc[0][s], sc[1][s]), fmaxf(sc[2][s], sc[3][s]));
            *(float4*)&Bs[tm*128 + tn*4]      = make_float4(m4[0],m4[1],m4[2],m4[3]);
            *(float4*)&Bs[tm*128 + 64 + tn*4] = make_float4(m4[4],m4[5],m4[6],m4[7]);
        }
        __syncthreads();
        float mx[8];
#pragma unroll
        for (int s = 0; s < 8; s++) {
            int col = (s < 4) ? tn*4 + s : 64 + tn*4 + (s-4);
            float a0 = Bs[(mb+0)*128 + col];
            float a1 = Bs[(mb+1)*128 + col];
            float a2 = Bs[(mb+2)*128 + col];
            float a3 = Bs[(mb+3)*128 + col];
            mx[s] = fmaxf(fmaxf(a0,a1), fmaxf(a2,a3));
        }
        float e[4][8], ps[8];
#pragma unroll
        for (int s = 0; s < 8; s++) {
            float p = 0.0f;
#pragma unroll
            for (int i = 0; i < 4; i++) { e[i][s] = expf(sc[i][s] - mx[s]); p += e[i][s]; }
            ps[s] = p;
        }
        *(float4*)&Bs[2048 + tm*128 + tn*4]      = make_float4(ps[0],ps[1],ps[2],ps[3]);
        *(float4*)&Bs[2048 + tm*128 + 64 + tn*4] = make_float4(ps[4],ps[5],ps[6],ps[7]);
        __syncthreads();
        float inv[8];
#pragma unroll
        for (int s = 0; s < 8; s++) {
            int col = (s < 4) ? tn*4 + s : 64 + tn*4 + (s-4);
            float su = Bs[2048 + (mb+0)*128 + col] + Bs[2048 + (mb+1)*128 + col]
                     + Bs[2048 + (mb+2)*128 + col] + Bs[2048 + (mb+3)*128 + col];
            inv[s] = 1.0f / su;
        }

        float pr[8];
#pragma unroll
        for (int s = 0; s < 8; s++) pr[s] = 0.0f;
        float* outA = out + (size_t)M1*DPf;
#pragma unroll
        for (int i = 0; i < 4; i++) {
            int r = tm*4 + i;
            const float* vp = g_vf + ((size_t)(b*NPTS + sidx[r]))*DMf;
            float a0 = e[i][0]*inv[0], a1 = e[i][1]*inv[1],
                  a2 = e[i][2]*inv[2], a3 = e[i][3]*inv[3];
            float a4 = e[i][4]*inv[4], a5 = e[i][5]*inv[5],
                  a6 = e[i][6]*inv[6], a7 = e[i][7]*inv[7];
            float4 v0 = *(const float4*)(vp + tn*4);
            float4 v1 = *(const float4*)(vp + 64 + tn*4);
            float4 p0 = *(const float4*)&As[r*PITCH + tn*4];
            float4 p1 = *(const float4*)&As[r*PITCH + 64 + tn*4];
            *(float4*)(outA + (bm + r)*128 + tn*4)      = make_float4(a0,a1,a2,a3);
            *(float4*)(outA + (bm + r)*128 + 64 + tn*4) = make_float4(a4,a5,a6,a7);
            pr[0] += a0*(v0.x+p0.x); pr[1] += a1*(v0.y+p0.y);
            pr[2] += a2*(v0.z+p0.z); pr[3] += a3*(v0.w+p0.w);
            pr[4] += a4*(v1.x+p1.x); pr[5] += a5*(v1.y+p1.y);
            pr[6] += a6*(v1.z+p1.z); pr[7] += a7*(v1.w+p1.w);
        }
        __syncthreads();
        *(float4*)&Bs[tm*128 + tn*4]      = make_float4(pr[0],pr[1],pr[2],pr[3]);
        *(float4*)&Bs[tm*128 + 64 + tn*4] = make_float4(pr[4],pr[5],pr[6],pr[7]);
        __syncthreads();

#pragma unroll
        for (int rep = 0; rep < 2; rep++) {
            int ii  = rep*256 + tid;
            int qq  = ii >> 7;
            int col = ii & 127;
            As[qq*128 + col] = Bs[(qq*4+0)*128 + col] + Bs[(qq*4+1)*128 + col]
                             + Bs[(qq*4+2)*128 + col] + Bs[(qq*4+3)*128 + col];
        }
        __syncthreads();

        {
            int qf = tid >> 6, f = tid & 63;
            const float* rp = As + qf*128;
            float o0 = 0.f, o1 = 0.f, o2 = 0.f, o3 = 0.f;
#pragma unroll 8
            for (int j = 0; j < 128; j += 4) {
                o0 += rp[j]   * fc2_w[ j   *DPf + f];
                o1 += rp[j+1] * fc2_w[(j+1)*DPf + f];
                o2 += rp[j+2] * fc2_w[(j+2)*DPf + f];
                o3 += rp[j+3] * fc2_w[(j+3)*DPf + f];
            }
            float o = fc2_b[f] + ((o0 + o1) + (o2 + o3))
                    + features[(size_t)(m0 + qf)*DPf + f];
            out[(size_t)(m0 + qf)*DPf + f] = o;
        }
    }
}

// ---------------- launch ----------------
extern "C" void kernel_launch(void* const* d_in, const int* in_sizes, int n_in,
                              void* d_out, int out_size) {
    const float* xyz   = (const float*)d_in[0];
    const float* feat  = (const float*)d_in[1];
    const float* fc1_w = (const float*)d_in[2];
    const float* fc1_b = (const float*)d_in[3];
    const float* fc2_w = (const float*)d_in[4];
    const float* fc2_b = (const float*)d_in[5];
    const float* d1_w  = (const float*)d_in[6];
    const float* d1_b  = (const float*)d_in[7];
    const float* d2_w  = (const float*)d_in[8];
    const float* d2_b  = (const float*)d_in[9];
    const float* g1_w  = (const float*)d_in[10];
    const float* g1_b  = (const float*)d_in[11];
    const float* g2_w  = (const float*)d_in[12];
    const float* g2_b  = (const float*)d_in[13];
    const float* wq_w  = (const float*)d_in[14];
    const float* wk_w  = (const float*)d_in[15];
    const float* wv_w  = (const float*)d_in[16];
    const float* sim_w = (const float*)d_in[17];
    const float* sim_b = (const float*)d_in[18];
    float* out = (float*)d_out;

    static float *p_x = nullptr, *p_q, *p_kf, *p_vf, *p_qs, *p_ks, *p_wqs, *p_wks;
    static cudaStream_t s2;
    static cudaEvent_t evFork, evJoin;
    static bool attr_done = false;
    const int MEGA_SMEM = MEGA_FLOATS * 4;   // 102928 B
    if (!attr_done) {
        cudaGetSymbolAddress((void**)&p_x,   g_x);
        cudaGetSymbolAddress((void**)&p_q,   g_q);
        cudaGetSymbolAddress((void**)&p_kf,  g_kf);
        cudaGetSymbolAddress((void**)&p_vf,  g_vf);
        cudaGetSymbolAddress((void**)&p_qs,  g_qs);
        cudaGetSymbolAddress((void**)&p_ks,  g_ks);
        cudaGetSymbolAddress((void**)&p_wqs, g_wqs);
        cudaGetSymbolAddress((void**)&p_wks, g_wks);
        cudaFuncSetAttribute(mega_kernel,
                             cudaFuncAttributeMaxDynamicSharedMemorySize, MEGA_SMEM);
        cudaStreamCreateWithFlags(&s2, cudaStreamNonBlocking);
        cudaEventCreateWithFlags(&evFork, cudaEventDisableTiming);
        cudaEventCreateWithFlags(&evJoin, cudaEventDisableTiming);
        attr_done = true;
    }

    // Fork: knn on side stream, GEMM chain on main stream (independent until mega).
    cudaEventRecord(evFork, 0);
    cudaStreamWaitEvent(s2, evFork, 0);

    // side stream: KNN
    knn_kernel<<<M1/4, 128, 0, s2>>>(xyz);
    cudaEventRecord(evJoin, s2);

    // main stream: combined weights, fc1, batch5
    gemm_small<<<dim3(1, 2), 256>>>(wq_w, DMf, DMf, sim_w + 128, nullptr, p_wqs,
                                    wk_w, sim_w + 128, p_wks);
    gemm_small<<<M1/128, 256>>>(feat, DPf, DPf, fc1_w, fc1_b, p_x,
                                nullptr, nullptr, nullptr);
    Batch5 bt;
    bt.W[0] = wq_w;  bt.C[0] = p_q;
    bt.W[1] = wk_w;  bt.C[1] = p_kf;
    bt.W[2] = wv_w;  bt.C[2] = p_vf;
    bt.W[3] = p_wqs; bt.C[3] = p_qs;
    bt.W[4] = p_wks; bt.C[4] = p_ks;
    gemm_batch5<<<dim3(M1/128, 5), 256>>>(p_x, bt);

    // Join: mega needs both g_idx (knn) and q/k/v/qs/ks (batch5)
    cudaStreamWaitEvent(0, evJoin, 0);
    mega_kernel<<<M1/4, 256, MEGA_SMEM>>>(xyz, d1_w, d1_b, d2_w, d2_b,
                                          sim_w, sim_b, g1_w, g1_b, g2_w, g2_b,
                                          fc2_w, fc2_b, feat, out);
}

// round 15
// speedup vs baseline: 1.0942x; 1.0171x over previous
#include <cuda_runtime.h>
#include <math.h>

#define NB 4
#define NPTS 4096
#define KNN 16
#define DPf 64
#define DMf 128
#define M1 (NB*NPTS)          /* 16384  */
#define M2 (M1*KNN)           /* 262144 */
#define EPSV 1e-8f
#define PITCH 132             /* smem tile pitch; 4*132=528 words, %32=16 -> conflict-free */
#define BROWS 64

// ---------------- scratch ----------------
__device__ float g_x [(size_t)M1*DMf];
__device__ float g_q [(size_t)M1*DMf];
__device__ float g_kf[(size_t)M1*DMf];
__device__ float g_vf[(size_t)M1*DMf];
__device__ float g_qs[(size_t)M1*DMf];   // x @ (wq@simw')
__device__ float g_ks[(size_t)M1*DMf];   // x @ (wk@simw')
__device__ float g_wqs[DMf*DMf];         // wq @ simw'
__device__ float g_wks[DMf*DMf];         // wk @ simw'
__device__ float g_pe[(size_t)M2*DMf];   // pos_enc (gmem round-trip)
__device__ int   g_idx[M1*KNN];

// ---------------- packed f32x2 helpers ----------------
__device__ __forceinline__ unsigned long long pack2(float x, float y) {
    unsigned long long r;
    asm("mov.b64 %0, {%1, %2};" : "=l"(r) : "f"(x), "f"(y));
    return r;
}
__device__ __forceinline__ float2 unpack2(unsigned long long v) {
    float2 f;
    asm("mov.b64 {%0, %1}, %2;" : "=f"(f.x), "=f"(f.y) : "l"(v));
    return f;
}
__device__ __forceinline__ void ffma2(unsigned long long& d,
                                      unsigned long long a,
                                      unsigned long long b) {
    asm("fma.rn.f32x2 %0, %1, %2, %0;" : "+l"(d) : "l"(a), "l"(b));
}

// ---------------- cp.async helpers ----------------
__device__ __forceinline__ unsigned smem_u32(const void* p) {
    unsigned a;
    asm("{ .reg .u64 t; cvta.to.shared.u64 t, %1; cvt.u32.u64 %0, t; }" : "=r"(a) : "l"(p));
    return a;
}
__device__ __forceinline__ void cpa16(unsigned dst, const void* src) {
    asm volatile("cp.async.ca.shared.global [%0], [%1], 16;" :: "r"(dst), "l"(src));
}
__device__ __forceinline__ void cpa_commit() { asm volatile("cp.async.commit_group;"); }
template<int N> __device__ __forceinline__ void cpa_wait() {
    asm volatile("cp.async.wait_group %0;" :: "n"(N));
}

// ---------------- KNN: warp per query, branchless register top-16 ----------------
__global__ void knn_kernel(const float* __restrict__ xyz) {
    int warp = threadIdx.x >> 5;
    int lane = threadIdx.x & 31;
    int row  = blockIdx.x * 4 + warp;
    int b = row >> 12;
    int n = row & (NPTS - 1);
    const float* xb = xyz + (size_t)b * NPTS * 3;
    float qx = xb[n*3+0], qy = xb[n*3+1], qz = xb[n*3+2];
    float sq = qx*qx + qy*qy + qz*qz;

    unsigned long long best[16];
#pragma unroll
    for (int i = 0; i < 16; i++) best[i] = ~0ULL;

    for (int t = 0; t < NPTS/32; t++) {
        int j = t*32 + lane;
        float x = xb[j*3+0], y = xb[j*3+1], z = xb[j*3+2];
        float sj = x*x + y*y + z*z;
        float d = sq + sj - 2.0f*(qx*x + qy*y + qz*z);
        unsigned u = __float_as_uint(d);
        u = (u & 0x80000000u) ? ~u : (u | 0x80000000u);
        unsigned long long key = ((unsigned long long)u << 32) | (unsigned)j;

        bool pi = key < best[15];
#pragma unroll
        for (int i = 15; i >= 1; i--) {
            bool pim = key < best[i-1];
            best[i] = pi ? (pim ? best[i-1] : key) : best[i];
            pi = pim;
        }
        best[0] = pi ? key : best[0];
    }

    __shared__ unsigned long long sh[4][512];
#pragma unroll
    for (int i = 0; i < 16; i++) sh[warp][lane*16 + i] = best[i];
    __syncwarp();

    int p = 0;
    for (int r = 0; r < 16; r++) {
        unsigned long long v = (p < 16) ? sh[warp][lane*16 + p] : ~0ULL;
        unsigned long long m = v;
#pragma unroll
        for (int off = 16; off; off >>= 1) {
            unsigned long long o = __shfl_xor_sync(0xffffffffu, m, off);
            m = (o < m) ? o : m;
        }
        if (v == m) { g_idx[row*KNN + r] = (int)(m & 0xffffffffu); p++; }
        __syncwarp();
    }
}

// ---------------- GEMM core (shared by variants) ----------------
__device__ __forceinline__ void gemm128_body(const float* __restrict__ A, int lda, int Ka,
                                             const float* __restrict__ W,
                                             const float* __restrict__ bias,
                                             float* __restrict__ C, int bm, int tid) {
    __shared__ float As[32][132];
    __shared__ float Ws[32][128];
    int tm = tid >> 4, tn = tid & 15;

    unsigned long long acc[8][4];
#pragma unroll
    for (int i = 0; i < 8; i++)
#pragma unroll
        for (int j = 0; j < 4; j++) acc[i][j] = 0ULL;

    for (int k0 = 0; k0 < Ka; k0 += 32) {
#pragma unroll
        for (int pss = 0; pss < 4; pss++) {
            int idx4 = pss*256 + tid;
            int r  = idx4 >> 3;
            int c4 = idx4 & 7;
            float4 v = *(const float4*)(A + (size_t)(bm + r)*lda + k0 + c4*4);
            As[c4*4+0][r] = v.x; As[c4*4+1][r] = v.y;
            As[c4*4+2][r] = v.z; As[c4*4+3][r] = v.w;
        }
#pragma unroll
        for (int pss = 0; pss < 4; pss++) {
            int idx4 = pss*256 + tid;
            int r  = idx4 >> 5;
            int c4 = idx4 & 31;
            *(float4*)&Ws[r][c4*4] = *(const float4*)(W + (size_t)(k0 + r)*128 + c4*4);
        }
        __syncthreads();
#pragma unroll
        for (int kk = 0; kk < 32; kk++) {
            float4 a0 = *(const float4*)&As[kk][tm*8];
            float4 a1 = *(const float4*)&As[kk][tm*8 + 4];
            ulonglong2 b01 = *(const ulonglong2*)&Ws[kk][tn*8];
            ulonglong2 b23 = *(const ulonglong2*)&Ws[kk][tn*8+4];
            unsigned long long av[8] = { pack2(a0.x, a0.x), pack2(a0.y, a0.y),
                                         pack2(a0.z, a0.z), pack2(a0.w, a0.w),
                                         pack2(a1.x, a1.x), pack2(a1.y, a1.y),
                                         pack2(a1.z, a1.z), pack2(a1.w, a1.w) };
#pragma unroll
            for (int i = 0; i < 8; i++) {
                ffma2(acc[i][0], av[i], b01.x);
                ffma2(acc[i][1], av[i], b01.y);
                ffma2(acc[i][2], av[i], b23.x);
                ffma2(acc[i][3], av[i], b23.y);
            }
        }
        __syncthreads();
    }

    float bia[8];
#pragma unroll
    for (int j = 0; j < 8; j++) bia[j] = bias ? bias[tn*8 + j] : 0.0f;

#pragma unroll
    for (int i = 0; i < 8; i++) {
        size_t row = (size_t)bm + tm*8 + i;
        float v[8];
#pragma unroll
        for (int j = 0; j < 4; j++) {
            float2 f = unpack2(acc[i][j]);
            v[2*j]   = f.x + bia[2*j];
            v[2*j+1] = f.y + bia[2*j+1];
        }
        float4* cp = (float4*)(C + row*128 + tn*8);
        cp[0] = make_float4(v[0], v[1], v[2], v[3]);
        cp[1] = make_float4(v[4], v[5], v[6], v[7]);
    }
}

// fc1 (and wqs/wks prep when gridDim.y==2 with W2/C2)
__global__ void __launch_bounds__(256, 2)
gemm_small(const float* __restrict__ A, int lda, int Ka,
           const float* __restrict__ W, const float* __restrict__ bias,
           float* __restrict__ C,
           const float* A2, const float* W2, float* C2) {
    if (blockIdx.y == 1) { A = A2; W = W2; C = C2; }
    gemm128_body(A, lda, Ka, W, bias, C, blockIdx.x * 128, threadIdx.x);
}

// batched 5-way: q,k,v,qs,ks all from x
struct Batch5 { const float* W[5]; float* C[5]; };
__global__ void __launch_bounds__(256, 2)
gemm_batch5(const float* __restrict__ A, Batch5 bt) {
    gemm128_body(A, DMf, DMf, bt.W[blockIdx.y], nullptr, bt.C[blockIdx.y],
                 blockIdx.x * 128, threadIdx.x);
}

// ---------------- mega kernel (single-tile, 3 CTAs/SM) ----------------
#define OFF_TS  0                               /* tile: 64 x PITCH = 8448 */
#define OFF_W   (BROWS*PITCH)                   /* 8448; 2 x (32x128) ping-pong */
#define OFF_QS  (OFF_W + 2*32*128)              /* 16640 */
#define OFF_SIM (OFF_QS + 512)                  /* 17152 */
#define OFF_QN  (OFF_SIM + 64)                  /* 17216 */
#define OFF_IDX (OFF_QN + 4)                    /* 17220 */
#define MEGA_FLOATS (OFF_IDX + 64)              /* 17284 -> 69136 B */

__device__ __forceinline__ void load_quarter(unsigned sW, const float* __restrict__ W,
                                             int quarter, int tid) {
    const float* src = W + (size_t)quarter*32*128;
#pragma unroll
    for (int it = 0; it < 4; it++) {
        int c = it*256 + tid;
        cpa16(sW + (unsigned)c*16u, src + c*4);
    }
}

__device__ __forceinline__ void mm32(const float* __restrict__ T, int kbase,
                                     const float* __restrict__ W,
                                     int tm, int tn,
                                     unsigned long long acc[4][4]) {
    const float* ap = T + tm*4*PITCH + kbase;
    const float* wp = W + tn*4;
#pragma unroll 4
    for (int kk = 0; kk < 32; kk += 2) {
        ulonglong2 B00 = *(const ulonglong2*)(wp + kk*128);
        ulonglong2 B01 = *(const ulonglong2*)(wp + kk*128 + 64);
        ulonglong2 B10 = *(const ulonglong2*)(wp + (kk+1)*128);
        ulonglong2 B11 = *(const ulonglong2*)(wp + (kk+1)*128 + 64);
#pragma unroll
        for (int i = 0; i < 4; i++) {
            float2 a = *(const float2*)(ap + i*PITCH + kk);
            unsigned long long av0 = pack2(a.x, a.x);
            unsigned long long av1 = pack2(a.y, a.y);
            ffma2(acc[i][0], av0, B00.x);
            ffma2(acc[i][1], av0, B00.y);
            ffma2(acc[i][2], av0, B01.x);
            ffma2(acc[i][3], av0, B01.y);
            ffma2(acc[i][0], av1, B10.x);
            ffma2(acc[i][1], av1, B10.y);
            ffma2(acc[i][2], av1, B11.x);
            ffma2(acc[i][3], av1, B11.y);
        }
    }
}

__global__ void __launch_bounds__(256, 3)
mega_kernel(const float* __restrict__ xyz,
            const float* __restrict__ d1_w, const float* __restrict__ d1_b,
            const float* __restrict__ d2_w, const float* __restrict__ d2_b,
            const float* __restrict__ sim_w, const float* __restrict__ sim_b,
            const float* __restrict__ g1_w, const float* __restrict__ g1_b,
            const float* __restrict__ g2_w, const float* __restrict__ g2_b,
            const float* __restrict__ fc2_w, const float* __restrict__ fc2_b,
            const float* __restrict__ features,
            float* __restrict__ out) {
    extern __shared__ float sm[];
    float* Ts   = sm + OFF_TS;     // h1 -> t -> h2 -> softmax scratch
    float* Wb   = sm + OFF_W;      // 2 x (32x128) ping-pong weight quarters
    float* Qs   = sm + OFF_QS;
    float* ssim = sm + OFF_SIM;
    float* sqn  = sm + OFF_QN;
    int*   sidx = (int*)(sm + OFF_IDX);
    unsigned sW = smem_u32(Wb);

    int tid  = threadIdx.x;
    int wid  = tid >> 5, lane = tid & 31;
    int tm   = tid >> 4, tn = tid & 15;
    int m0   = blockIdx.x * 4;
    size_t bm = (size_t)blockIdx.x * BROWS;
    int b    = m0 >> 12;

    const float* Wseq[3] = { d2_w, g1_w, g2_w };

    load_quarter(sW, Wseq[0], 0, tid);
    cpa_commit();
    load_quarter(sW + 4096u*4u, Wseq[0], 1, tid);
    cpa_commit();

    // ---- gather prologue: h1 -> Ts ----
    if (tid < 64) sidx[tid] = g_idx[m0*KNN + tid];
    {
        float2 v = *(const float2*)(g_q + (size_t)m0*DMf + tid*2);
        *(float2*)(Qs + tid*2) = v;
    }
    __syncthreads();

    if (wid < 4) {
        float4 qf = *(const float4*)(Qs + wid*128 + lane*4);
        float s = qf.x*qf.x + qf.y*qf.y + qf.z*qf.z + qf.w*qf.w;
#pragma unroll
        for (int off = 16; off; off >>= 1) s += __shfl_xor_sync(0xffffffffu, s, off);
        if (lane == 0) sqn[wid] = fmaxf(sqrtf(s), EPSV);
    }
    __syncthreads();

    float4 w0 = *(const float4*)(d1_w + lane*4);
    float4 w1 = *(const float4*)(d1_w + 128 + lane*4);
    float4 w2 = *(const float4*)(d1_w + 256 + lane*4);
    float4 db = *(const float4*)(d1_b + lane*4);
    const float* xb = xyz + (size_t)b*NPTS*3;

#pragma unroll 1
    for (int it = 0; it < 8; it++) {
        int j   = it*8 + wid;
        int row = j >> 4;
        int n   = (m0 + row) & (NPTS - 1);
        int idx = sidx[j];

        float4 kf = *(const float4*)(g_kf + ((size_t)(b*NPTS + idx))*DMf + lane*4);
        float4 qf = *(const float4*)(Qs + row*128 + lane*4);
        float dq = qf.x*kf.x + qf.y*kf.y + qf.z*kf.z + qf.w*kf.w;
        float dk = kf.x*kf.x + kf.y*kf.y + kf.z*kf.z + kf.w*kf.w;
#pragma unroll
        for (int off = 16; off; off >>= 1) {
            dq += __shfl_xor_sync(0xffffffffu, dq, off);
            dk += __shfl_xor_sync(0xffffffffu, dk, off);
        }
        float kn = fmaxf(sqrtf(dk), EPSV);
        if (lane == 0) ssim[j] = dq / (sqn[row] * kn);

        float cx = xb[n*3+0] - xb[idx*3+0];
        float cy = xb[n*3+1] - xb[idx*3+1];
        float cz = xb[n*3+2] - xb[idx*3+2];
        float4 h;
        h.x = fmaxf(cx*w0.x + cy*w1.x + cz*w2.x + db.x, 0.0f);
        h.y = fmaxf(cx*w0.y + cy*w1.y + cz*w2.y + db.y, 0.0f);
        h.z = fmaxf(cx*w0.z + cy*w1.z + cz*w2.z + db.z, 0.0f);
        h.w = fmaxf(cx*w0.w + cy*w1.w + cz*w2.w + db.w, 0.0f);
        *(float4*)(Ts + j*PITCH + lane*4) = h;
    }

    // ---- 3-GEMM chain in one tile; two syncs per quarter protect in-place reuse ----
    unsigned long long acc[4][4];
#pragma unroll
    for (int i = 0; i < 4; i++)
#pragma unroll
        for (int j = 0; j < 4; j++) acc[i][j] = 0ULL;

    int ch = 0;
    for (int g = 0; g < 3; g++) {
        if (g >= 1) {
#pragma unroll
            for (int i = 0; i < 4; i++)
#pragma unroll
                for (int j = 0; j < 4; j++) acc[i][j] = 0ULL;
        }
        for (int q = 0; q < 4; q++) {
            if (ch < 11) cpa_wait<1>(); else cpa_wait<0>();
            __syncthreads();
            mm32(Ts, q*32, Wb + (ch & 1)*4096, tm, tn, acc);
            __syncthreads();
            int nxt = ch + 2;
            if (nxt < 12) {
                load_quarter(sW + (unsigned)((nxt & 1)*4096)*4u, Wseq[nxt >> 2], nxt & 3, tid);
                cpa_commit();
            }
            ch++;
        }

        if (g == 0) {
            // epi1: pe = acc + d2_b -> gmem ; t = pe + qs[m] - ks[idx] + sim*sw0 + sim_b -> Ts
            float4 b0 = *(const float4*)(d2_b + tn*4);
            float4 b1 = *(const float4*)(d2_b + 64 + tn*4);
            float4 sb0 = *(const float4*)(sim_b + tn*4);
            float4 sb1 = *(const float4*)(sim_b + 64 + tn*4);
            float4 s0 = *(const float4*)(sim_w + tn*4);
            float4 s1 = *(const float4*)(sim_w + 64 + tn*4);
            float bb[8]  = {b0.x,b0.y,b0.z,b0.w,b1.x,b1.y,b1.z,b1.w};
            float sbb[8] = {sb0.x,sb0.y,sb0.z,sb0.w,sb1.x,sb1.y,sb1.z,sb1.w};
            float sw[8]  = {s0.x,s0.y,s0.z,s0.w,s1.x,s1.y,s1.z,s1.w};
#pragma unroll
            for (int i = 0; i < 4; i++) {
                int r = tm*4 + i;
                float sv = ssim[r];
                const float* qsp = g_qs + (size_t)(m0 + (r >> 4))*DMf;
                const float* ksp = g_ks + ((size_t)(b*NPTS + sidx[r]))*DMf;
                float4 q0 = *(const float4*)(qsp + tn*4);
                float4 q1 = *(const float4*)(qsp + 64 + tn*4);
                float4 k0 = *(const float4*)(ksp + tn*4);
                float4 k1 = *(const float4*)(ksp + 64 + tn*4);
                float qs8[8] = {q0.x,q0.y,q0.z,q0.w,q1.x,q1.y,q1.z,q1.w};
                float ks8[8] = {k0.x,k0.y,k0.z,k0.w,k1.x,k1.y,k1.z,k1.w};
                float pe[8], t[8];
#pragma unroll
                for (int j = 0; j < 4; j++) {
                    float2 f = unpack2(acc[i][j]);
                    pe[2*j]   = f.x + bb[2*j];
                    pe[2*j+1] = f.y + bb[2*j+1];
                }
#pragma unroll
                for (int s = 0; s < 8; s++)
                    t[s] = pe[s] + qs8[s] - ks8[s] + sv*sw[s] + sbb[s];
                *(float4*)(g_pe + (bm + r)*128 + tn*4)      = make_float4(pe[0],pe[1],pe[2],pe[3]);
                *(float4*)(g_pe + (bm + r)*128 + 64 + tn*4) = make_float4(pe[4],pe[5],pe[6],pe[7]);
                *(float4*)&Ts[r*PITCH + tn*4]      = make_float4(t[0],t[1],t[2],t[3]);
                *(float4*)&Ts[r*PITCH + 64 + tn*4] = make_float4(t[4],t[5],t[6],t[7]);
            }
        } else if (g == 1) {
            // epi2: relu(+g1_b); h2 -> Ts
            float4 b0 = *(const float4*)(g1_b + tn*4);
            float4 b1 = *(const float4*)(g1_b + 64 + tn*4);
            float bb[8] = {b0.x,b0.y,b0.z,b0.w,b1.x,b1.y,b1.z,b1.w};
#pragma unroll
            for (int i = 0; i < 4; i++) {
                int r = tm*4 + i;
                float v[8];
#pragma unroll
                for (int j = 0; j < 4; j++) {
                    float2 f = unpack2(acc[i][j]);
                    v[2*j]   = fmaxf(f.x + bb[2*j],   0.0f);
                    v[2*j+1] = fmaxf(f.y + bb[2*j+1], 0.0f);
                }
                *(float4*)&Ts[r*PITCH + tn*4]      = make_float4(v[0],v[1],v[2],v[3]);
                *(float4*)&Ts[r*PITCH + 64 + tn*4] = make_float4(v[4],v[5],v[6],v[7]);
            }
        }
    }
    __syncthreads();   // g2 mm32 done everywhere before Ts reuse below

    // ---- epilogue: softmax(k) + attn out + weighted sum + fc2 + residual ----
    {
        const float scale = 0.08838834764831845f;   // 1/sqrt(128)
        int q = tm >> 2;
        int mb = q*4;

        float sc[4][8];
        {
            float4 b0 = *(const float4*)(g2_b + tn*4);
            float4 b1 = *(const float4*)(g2_b + 64 + tn*4);
            float bb[8] = {b0.x,b0.y,b0.z,b0.w,b1.x,b1.y,b1.z,b1.w};
#pragma unroll
            for (int i = 0; i < 4; i++)
#pragma unroll
                for (int j = 0; j < 4; j++) {
                    float2 f = unpack2(acc[i][j]);
                    sc[i][2*j]   = (f.x + bb[2*j])   * scale;
                    sc[i][2*j+1] = (f.y + bb[2*j+1]) * scale;
                }
        }
        {
            float m4[8];
#pragma unroll
            for (int s = 0; s < 8; s++)
                m4[s] = fmaxf(fmaxf(sc[0][s], sc[1][s]), fmaxf(sc[2][s], sc[3][s]));
            *(float4*)&Ts[tm*128 + tn*4]      = make_float4(m4[0],m4[1],m4[2],m4[3]);
            *(float4*)&Ts[tm*128 + 64 + tn*4] = make_float4(m4[4],m4[5],m4[6],m4[7]);
        }
        __syncthreads();
        float mx[8];
#pragma unroll
        for (int s = 0; s < 8; s++) {
            int col = (s < 4) ? tn*4 + s : 64 + tn*4 + (s-4);
            float a0 = Ts[(mb+0)*128 + col];
            float a1 = Ts[(mb+1)*128 + col];
            float a2 = Ts[(mb+2)*128 + col];
            float a3 = Ts[(mb+3)*128 + col];
            mx[s] = fmaxf(fmaxf(a0,a1), fmaxf(a2,a3));
        }
        float e[4][8], ps[8];
#pragma unroll
        for (int s = 0; s < 8; s++) {
            float p = 0.0f;
#pragma unroll
            for (int i = 0; i < 4; i++) { e[i][s] = expf(sc[i][s] - mx[s]); p += e[i][s]; }
            ps[s] = p;
        }
        *(float4*)&Ts[2048 + tm*128 + tn*4]      = make_float4(ps[0],ps[1],ps[2],ps[3]);
        *(float4*)&Ts[2048 + tm*128 + 64 + tn*4] = make_float4(ps[4],ps[5],ps[6],ps[7]);
        __syncthreads();
        float inv[8];
#pragma unroll
        for (int s = 0; s < 8; s++) {
            int col = (s < 4) ? tn*4 + s : 64 + tn*4 + (s-4);
            float su = Ts[2048 + (mb+0)*128 + col] + Ts[2048 + (mb+1)*128 + col]
                     + Ts[2048 + (mb+2)*128 + col] + Ts[2048 + (mb+3)*128 + col];
            inv[s] = 1.0f / su;
        }

        float pr[8];
#pragma unroll
        for (int s = 0; s < 8; s++) pr[s] = 0.0f;
        float* outA = out + (size_t)M1*DPf;
#pragma unroll
        for (int i = 0; i < 4; i++) {
            int r = tm*4 + i;
            const float* vp = g_vf + ((size_t)(b*NPTS + sidx[r]))*DMf;
            const float* pp = g_pe + (bm + r)*128;
            float a0 = e[i][0]*inv[0], a1 = e[i][1]*inv[1],
                  a2 = e[i][2]*inv[2], a3 = e[i][3]*inv[3];
            float a4 = e[i][4]*inv[4], a5 = e[i][5]*inv[5],
                  a6 = e[i][6]*inv[6], a7 = e[i][7]*inv[7];
            float4 v0 = *(const float4*)(vp + tn*4);
            float4 v1 = *(const float4*)(vp + 64 + tn*4);
            float4 p0 = *(const float4*)(pp + tn*4);
            float4 p1 = *(const float4*)(pp + 64 + tn*4);
            *(float4*)(outA + (bm + r)*128 + tn*4)      = make_float4(a0,a1,a2,a3);
            *(float4*)(outA + (bm + r)*128 + 64 + tn*4) = make_float4(a4,a5,a6,a7);
            pr[0] += a0*(v0.x+p0.x); pr[1] += a1*(v0.y+p0.y);
            pr[2] += a2*(v0.z+p0.z); pr[3] += a3*(v0.w+p0.w);
            pr[4] += a4*(v1.x+p1.x); pr[5] += a5*(v1.y+p1.y);
            pr[6] += a6*(v1.z+p1.z); pr[7] += a7*(v1.w+p1.w);
        }
        __syncthreads();
        *(float4*)&Ts[tm*128 + tn*4]      = make_float4(pr[0],pr[1],pr[2],pr[3]);
        *(float4*)&Ts[tm*128 + 64 + tn*4] = make_float4(pr[4],pr[5],pr[6],pr[7]);
        __syncthreads();

#pragma unroll
        for (int rep = 0; rep < 2; rep++) {
            int ii  = rep*256 + tid;
            int qq  = ii >> 7;
            int col = ii & 127;
            Ts[4096 + qq*128 + col] = Ts[(qq*4+0)*128 + col] + Ts[(qq*4+1)*128 + col]
                                    + Ts[(qq*4+2)*128 + col] + Ts[(qq*4+3)*128 + col];
        }
        __syncthreads();

        {
            int qf = tid >> 6, f = tid & 63;
            const float* rp = Ts + 4096 + qf*128;
            float o0 = 0.f, o1 = 0.f, o2 = 0.f, o3 = 0.f;
#pragma unroll 8
            for (int j = 0; j < 128; j += 4) {
                o0 += rp[j]   * fc2_w[ j   *DPf + f];
                o1 += rp[j+1] * fc2_w[(j+1)*DPf + f];
                o2 += rp[j+2] * fc2_w[(j+2)*DPf + f];
                o3 += rp[j+3] * fc2_w[(j+3)*DPf + f];
            }
            float o = fc2_b[f] + ((o0 + o1) + (o2 + o3))
                    + features[(size_t)(m0 + qf)*DPf + f];
            out[(size_t)(m0 + qf)*DPf + f] = o;
        }
    }
}

// ---------------- launch ----------------
extern "C" void kernel_launch(void* const* d_in, const int* in_sizes, int n_in,
                              void* d_out, int out_size) {
    const float* xyz   = (const float*)d_in[0];
    const float* feat  = (const float*)d_in[1];
    const float* fc1_w = (const float*)d_in[2];
    const float* fc1_b = (const float*)d_in[3];
    const float* fc2_w = (const float*)d_in[4];
    const float* fc2_b = (const float*)d_in[5];
    const float* d1_w  = (const float*)d_in[6];
    const float* d1_b  = (const float*)d_in[7];
    const float* d2_w  = (const float*)d_in[8];
    const float* d2_b  = (const float*)d_in[9];
    const float* g1_w  = (const float*)d_in[10];
    const float* g1_b  = (const float*)d_in[11];
    const float* g2_w  = (const float*)d_in[12];
    const float* g2_b  = (const float*)d_in[13];
    const float* wq_w  = (const float*)d_in[14];
    const float* wk_w  = (const float*)d_in[15];
    const float* wv_w  = (const float*)d_in[16];
    const float* sim_w = (const float*)d_in[17];
    const float* sim_b = (const float*)d_in[18];
    float* out = (float*)d_out;

    static float *p_x = nullptr, *p_q, *p_kf, *p_vf, *p_qs, *p_ks, *p_wqs, *p_wks;
    static bool attr_done = false;
    const int MEGA_SMEM = MEGA_FLOATS * 4;   // 69136 B
    if (!attr_done) {
        cudaGetSymbolAddress((void**)&p_x,   g_x);
        cudaGetSymbolAddress((void**)&p_q,   g_q);
        cudaGetSymbolAddress((void**)&p_kf,  g_kf);
        cudaGetSymbolAddress((void**)&p_vf,  g_vf);
        cudaGetSymbolAddress((void**)&p_qs,  g_qs);
        cudaGetSymbolAddress((void**)&p_ks,  g_ks);
        cudaGetSymbolAddress((void**)&p_wqs, g_wqs);
        cudaGetSymbolAddress((void**)&p_wks, g_wks);
        cudaFuncSetAttribute(mega_kernel,
                             cudaFuncAttributeMaxDynamicSharedMemorySize, MEGA_SMEM);
        attr_done = true;
    }

    // 0) KNN
    knn_kernel<<<M1/4, 128>>>(xyz);

    // 0b) combined weights: wqs = wq@simw', wks = wk@simw'
    gemm_small<<<dim3(1, 2), 256>>>(wq_w, DMf, DMf, sim_w + 128, nullptr, p_wqs,
                                    wk_w, sim_w + 128, p_wks);

    // 1) x = features @ fc1 + b
    gemm_small<<<M1/128, 256>>>(feat, DPf, DPf, fc1_w, fc1_b, p_x,
                                nullptr, nullptr, nullptr);

    // 2) q, k, v, qs, ks
    Batch5 bt;
    bt.W[0] = wq_w;  bt.C[0] = p_q;
    bt.W[1] = wk_w;  bt.C[1] = p_kf;
    bt.W[2] = wv_w;  bt.C[2] = p_vf;
    bt.W[3] = p_wqs; bt.C[3] = p_qs;
    bt.W[4] = p_wks; bt.C[4] = p_ks;
    gemm_batch5<<<dim3(M1/128, 5), 256>>>(p_x, bt);

    // 3) mega (single-tile, 3 CTAs/SM)
    mega_kernel<<<M1/4, 256, MEGA_SMEM>>>(xyz, d1_w, d1_b, d2_w, d2_b,
                                          sim_w, sim_b, g1_w, g1_b, g2_w, g2_b,
                                          fc2_w, fc2_b, feat, out);
}